// round 15
// baseline (speedup 1.0000x reference)
#include <cuda_runtime.h>
#include <cstdint>
#include <math.h>

#define Tt 256
#define NEGV -1e10f
#define EPSC 1e-4f
#define LOG2PI 1.8378770664093453f
#define NJOBS 8448
#define FU_SMEMB 84480

typedef unsigned long long ull;
typedef unsigned int u32;

#define PACK2(out, x) asm("mov.b64 %0, {%1, %1};" : "=l"(out) : "r"(__float_as_uint(x)))
#define UNPK(lo, hi, in) { unsigned int ulo, uhi; \
    asm("mov.b64 {%0, %1}, %2;" : "=r"(ulo), "=r"(uhi) : "l"(in)); \
    lo = __uint_as_float(ulo); hi = __uint_as_float(uhi); }
#define FMA2(d, a, b) asm("fma.rn.f32x2 %0, %1, %2, %0;" : "+l"(d) : "l"(a), "l"(b))
#define ADD2(d, a, b) asm("add.rn.f32x2 %0, %1, %2;" : "=l"(d) : "l"(a), "l"(b))

__device__ __forceinline__ u32 bf16_bits(float a) {
    u32 u = __float_as_uint(a);
    return (u + 0x7FFFu + ((u >> 16) & 1u)) >> 16;
}
__device__ __forceinline__ void bfsplit2(float a0, float a1, u32& hi, u32& lo) {
    u32 h0 = bf16_bits(a0);
    u32 h1 = bf16_bits(a1);
    float h0f = __uint_as_float(h0 << 16);
    float h1f = __uint_as_float(h1 << 16);
    u32 l0 = bf16_bits(a0 - h0f);
    u32 l1 = bf16_bits(a1 - h1f);
    hi = (h1 << 16) | h0;
    lo = (l1 << 16) | l0;
}
__device__ __forceinline__ u32 smem_to_u32(const void* p) {
    u32 a;
    asm("{ .reg .u64 t; cvta.to.shared.u64 t, %1; cvt.u32.u64 %0, t; }"
        : "=r"(a) : "l"(p));
    return a;
}
__device__ __forceinline__ void ldmx4(u32& r0, u32& r1, u32& r2, u32& r3, u32 addr) {
    asm volatile("ldmatrix.sync.aligned.m8n8.x4.shared.b16 {%0,%1,%2,%3}, [%4];"
                 : "=r"(r0), "=r"(r1), "=r"(r2), "=r"(r3) : "r"(addr));
}
__device__ __forceinline__ void mma_bf16(float* c, const u32* a, const u32* b) {
    asm volatile("mma.sync.aligned.m16n8k16.row.col.f32.bf16.bf16.f32 "
                 "{%0,%1,%2,%3}, {%4,%5,%6,%7}, {%8,%9}, {%0,%1,%2,%3};"
                 : "+f"(c[0]), "+f"(c[1]), "+f"(c[2]), "+f"(c[3])
                 : "r"(a[0]), "r"(a[1]), "r"(a[2]), "r"(a[3]),
                   "r"(b[0]), "r"(b[1]));
}
__device__ __forceinline__ void cpa16(u32 s, const void* g) {
    asm volatile("cp.async.cg.shared.global [%0], [%1], 16;"
                 :: "r"(s), "l"(g) : "memory");
}
__device__ __forceinline__ void cpa_commit() {
    asm volatile("cp.async.commit_group;" ::: "memory");
}
__device__ __forceinline__ void cpa_wait0() {
    asm volatile("cp.async.wait_group 0;" ::: "memory");
}

// ---------------- device scratch ----------------
__device__ float g_W0T[96 * 256];
__device__ float g_bsum[2048];
__device__ float g_ARX[2048 * 96];
__device__ float g_PRE0[2048 * 256];
__device__ float g_PRE[2048 * 256];
__device__ float g_GI[2048 * 2048];
__device__ float g_ZI[1024 * 256];
__device__ float g_H[2048 * 512];
__device__ float g_OW0MT[512 * 256];
__device__ float g_hping[2 * 4096];
__device__ float g_EMa[2048 * 128];
__device__ float g_EMb[2048 * 128];
__device__ float g_LS[2048 * 128];
__device__ float g_LM[2048 * 128];
__device__ float g_ob2perm[192];
__device__ u32 g_W1sp_h[256 * 128];
__device__ u32 g_W1sp_l[256 * 128];
__device__ u32 g_WIHsp_h[2048 * 128];
__device__ u32 g_WIHsp_l[2048 * 128];
__device__ u32 g_OW0Esp_h[256 * 256];
__device__ u32 g_OW0Esp_l[256 * 256];
__device__ unsigned short g_B1h[256 * 256];
__device__ unsigned short g_B2h[192 * 256];
__device__ u32 g_A1h[(size_t)2048 * 128 * 128];
__device__ u32 g_A1l[(size_t)2048 * 128 * 128];
__device__ u32 g_A2h[(size_t)2048 * 128 * 128];
__device__ u32 g_A2l[(size_t)2048 * 128 * 128];
__device__ int g_grp[8 * 32];
__device__ int g_master[32];
__device__ int g_release;
__device__ int g_jobctr;
__device__ int g_hpdone[256];
__device__ int g_tbdone[2048];
__device__ int g_emdone[256];

__device__ __forceinline__ float sigf(float x) { return 1.f / (1.f + __expf(-x)); }

// ---------------- prep ----------------
__global__ void k_prep(const float* __restrict__ w0, const float* __restrict__ w1p,
                       const float* __restrict__ wih, const float* __restrict__ ow0,
                       const float* __restrict__ ow1, const float* __restrict__ ow2,
                       const float* __restrict__ ob2, const float* __restrict__ bih,
                       const float* __restrict__ bhh, const float* __restrict__ mels) {
    int stride = gridDim.x * blockDim.x;
    int t0 = blockIdx.x * blockDim.x + threadIdx.x;
    for (int i = t0; i < 96 * 256; i += stride) {
        int k = i >> 8, p = i & 255;
        g_W0T[i] = (k < 80) ? w0[p * 80 + k] : 0.f;
    }
    for (int i = t0; i < 2048; i += stride) g_bsum[i] = bih[i] + bhh[i];
    for (int i = t0; i < 2048 * 96; i += stride) {
        int row = i / 96, d = i % 96;
        int t = row >> 3, b = row & 7;
        g_ARX[i] = (d < 80 && t > 0) ? mels[(b * 80 + d) * 256 + (t - 1)] : 0.f;
    }
    if (t0 < 8 * 32) g_grp[t0] = 0;
    if (t0 < 32) g_master[t0] = 0;
    if (t0 == 0) { g_release = 0; g_jobctr = 0; }
    if (t0 < 256) { g_hpdone[t0] = 0; g_emdone[t0] = 0; }
    for (int i = t0; i < 2048; i += stride) g_tbdone[i] = 0;
    for (int i = t0; i < 256 * 128; i += stride) {
        int n = i >> 7, kp = i & 127;
        u32 hi, lo;
        bfsplit2(w1p[n * 256 + 2 * kp], w1p[n * 256 + 2 * kp + 1], hi, lo);
        g_W1sp_h[i] = hi; g_W1sp_l[i] = lo;
    }
    for (int i = t0; i < 2048 * 128; i += stride) {
        int n = i >> 7, kp = i & 127;
        u32 hi, lo;
        bfsplit2(wih[n * 256 + 2 * kp], wih[n * 256 + 2 * kp + 1], hi, lo);
        g_WIHsp_h[i] = hi; g_WIHsp_l[i] = lo;
    }
    for (int i = t0; i < 256 * 256; i += stride) {
        int n = i >> 8, kp = i & 255;
        u32 hi, lo;
        bfsplit2(ow0[n * 1024 + 2 * kp], ow0[n * 1024 + 2 * kp + 1], hi, lo);
        g_OW0Esp_h[i] = hi; g_OW0Esp_l[i] = lo;
    }
    for (int i = t0; i < 512 * 256; i += stride) {
        int m = i >> 8, n = i & 255;
        g_OW0MT[i] = ow0[n * 1024 + 512 + m];
    }
    for (int i = t0; i < 65536; i += stride)
        g_B1h[i] = (unsigned short)bf16_bits(ow1[i]);
    for (int i = t0; i < 192 * 256; i += stride) {
        int n = i >> 8, k = i & 255;
        float w = 0.f;
        if (n < 160) {
            int sf = (n & 1) ? (80 + (n >> 1)) : (n >> 1);
            w = ow2[sf * 256 + k];
        } else if (n == 160) {
            w = ow2[160 * 256 + k];
        }
        g_B2h[i] = (unsigned short)bf16_bits(w);
    }
    for (int i = t0; i < 192; i += stride) {
        float v = 0.f;
        if (i < 160) v = ob2[(i & 1) ? (80 + (i >> 1)) : (i >> 1)];
        else if (i == 160) v = ob2[160];
        g_ob2perm[i] = v;
    }
}

// ---------------- f32x2 SGEMM (PRE0 only) ----------------
template <int ACT>
__global__ __launch_bounds__(256) void k_gemm(float* __restrict__ Cm,
                                              const float* __restrict__ Am,
                                              const float* __restrict__ BT,
                                              const float* __restrict__ bias,
                                              int R, int Ccols, int K) {
    __shared__ __align__(16) float As[32 * 68];
    __shared__ __align__(16) float Bs[32 * 128];
    int row0 = blockIdx.y * 64, col0 = blockIdx.x * 128;
    int tid = threadIdx.x;
    int tr = tid >> 4, tc = tid & 15;
    int r0 = tr * 4, c0 = tc * 8;
    ull acc0[8], acc1[8];
#pragma unroll
    for (int c = 0; c < 8; c++) { acc0[c] = 0ull; acc1[c] = 0ull; }
    for (int kt = 0; kt < K; kt += 32) {
        for (int i = tid; i < 2048; i += 256) {
            int r = i >> 5, k = i & 31;
            As[k * 68 + r] = Am[(row0 + r) * K + kt + k];
        }
        for (int i = tid; i < 4096; i += 256) {
            int k = i >> 7, c = i & 127;
            Bs[k * 128 + c] = BT[(kt + k) * Ccols + col0 + c];
        }
        __syncthreads();
#pragma unroll 8
        for (int k = 0; k < 32; k++) {
            ulonglong2 ap = *(const ulonglong2*)&As[k * 68 + r0];
            float4 b0 = *(const float4*)&Bs[k * 128 + c0];
            float4 b1 = *(const float4*)&Bs[k * 128 + c0 + 4];
            float wf[8] = {b0.x, b0.y, b0.z, b0.w, b1.x, b1.y, b1.z, b1.w};
#pragma unroll
            for (int c = 0; c < 8; c++) {
                ull wp;
                PACK2(wp, wf[c]);
                FMA2(acc0[c], ap.x, wp);
                FMA2(acc1[c], ap.y, wp);
            }
        }
        __syncthreads();
    }
#pragma unroll
    for (int c = 0; c < 8; c++) {
        int cc = col0 + c0 + c;
        float bb = bias ? bias[cc] : 0.f;
        float v0, v1, v2, v3;
        UNPK(v0, v1, acc0[c]);
        UNPK(v2, v3, acc1[c]);
        v0 += bb; v1 += bb; v2 += bb; v3 += bb;
        if (ACT) { v0 = fmaxf(v0, 0.f); v1 = fmaxf(v1, 0.f);
                   v2 = fmaxf(v2, 0.f); v3 = fmaxf(v3, 0.f); }
        Cm[(row0 + r0 + 0) * Ccols + cc] = v0;
        Cm[(row0 + r0 + 1) * Ccols + cc] = v1;
        Cm[(row0 + r0 + 2) * Ccols + cc] = v2;
        Cm[(row0 + r0 + 3) * Ccols + cc] = v3;
    }
}

// ---------------- generic HMMA GEMM (PRE, GI, ZI; 3-term) ----------------
#define HG_SMEMB 73728

template <int RELU>
__global__ __launch_bounds__(256, 1) void k_hgemm(float* __restrict__ Cm,
                                                  const float* __restrict__ Am,
                                                  const u32* __restrict__ Bh,
                                                  const u32* __restrict__ Bl,
                                                  const float* __restrict__ bias,
                                                  int Ccols, int K) {
    extern __shared__ __align__(16) char smh[];
    u32 sbase = smem_to_u32(smh);
    u32* Ah32 = (u32*)smh;
    u32* Al32 = (u32*)(smh + 18432);
    u32* Bh32 = (u32*)(smh + 36864);
    u32* Bl32 = (u32*)(smh + 55296);
    int row0 = blockIdx.y * 128, col0 = blockIdx.x * 128;
    int tid = threadIdx.x;
    int warp = tid >> 5, lane = tid & 31;
    int wr = (warp & 3) * 32;
    int wc = (warp >> 2) * 64;
    int Kh = K >> 1;
    float acc[2][8][4];
#pragma unroll
    for (int mt = 0; mt < 2; mt++)
#pragma unroll
        for (int nt = 0; nt < 8; nt++)
#pragma unroll
            for (int q = 0; q < 4; q++) acc[mt][nt][q] = 0.f;
    u32 lmrow = (u32)(lane & 15);
    u32 lmk = (u32)((lane >> 4) << 3);

    for (int kc = 0; kc < (K >> 6); kc++) {
        int k0 = kc * 64;
        for (int i = tid; i < 4096; i += 256) {
            int r = i >> 5, kp = i & 31;
            float2 av = *(const float2*)&Am[(size_t)(row0 + r) * K + k0 + 2 * kp];
            u32 hi, lo;
            bfsplit2(av.x, av.y, hi, lo);
            Ah32[r * 36 + kp] = hi;
            Al32[r * 36 + kp] = lo;
        }
        for (int i = tid; i < 4096; i += 256) {
            int n = i >> 5, kp = i & 31;
            size_t gsrc = (size_t)(col0 + n) * Kh + (k0 >> 1) + kp;
            Bh32[n * 36 + kp] = Bh[gsrc];
            Bl32[n * 36 + kp] = Bl[gsrc];
        }
        __syncthreads();
#pragma unroll
        for (int ks = 0; ks < 4; ks++) {
            u32 kk = (u32)(ks * 16);
            u32 a_h[2][4], a_l[2][4];
#pragma unroll
            for (int mt = 0; mt < 2; mt++) {
                u32 ad = sbase + (((u32)(wr + mt * 16) + lmrow) * 72 + kk + lmk) * 2;
                ldmx4(a_h[mt][0], a_h[mt][1], a_h[mt][2], a_h[mt][3], ad);
                ldmx4(a_l[mt][0], a_l[mt][1], a_l[mt][2], a_l[mt][3], ad + 18432);
            }
            u32 b_h[8][2], b_l[8][2];
#pragma unroll
            for (int np = 0; np < 4; np++) {
                u32 bd = sbase + 36864 +
                         (((u32)(wc + np * 16) + lmrow) * 72 + kk + lmk) * 2;
                u32 r0, r1, r2, r3;
                ldmx4(r0, r1, r2, r3, bd);
                b_h[np * 2][0] = r0; b_h[np * 2][1] = r2;
                b_h[np * 2 + 1][0] = r1; b_h[np * 2 + 1][1] = r3;
                ldmx4(r0, r1, r2, r3, bd + 18432);
                b_l[np * 2][0] = r0; b_l[np * 2][1] = r2;
                b_l[np * 2 + 1][0] = r1; b_l[np * 2 + 1][1] = r3;
            }
#pragma unroll
            for (int mt = 0; mt < 2; mt++)
#pragma unroll
                for (int nt = 0; nt < 8; nt++) {
                    mma_bf16(acc[mt][nt], a_h[mt], b_h[nt]);
                    mma_bf16(acc[mt][nt], a_l[mt], b_h[nt]);
                    mma_bf16(acc[mt][nt], a_h[mt], b_l[nt]);
                }
        }
        __syncthreads();
    }
#pragma unroll
    for (int mt = 0; mt < 2; mt++) {
        int r = wr + mt * 16 + (lane >> 2);
#pragma unroll
        for (int nt = 0; nt < 8; nt++) {
            int gc = col0 + wc + nt * 8 + (lane & 3) * 2;
            float bb0 = bias ? bias[gc] : 0.f;
            float bb1 = bias ? bias[gc + 1] : 0.f;
            float v0 = acc[mt][nt][0] + bb0;
            float v1 = acc[mt][nt][1] + bb1;
            float v2 = acc[mt][nt][2] + bb0;
            float v3 = acc[mt][nt][3] + bb1;
            if (RELU) { v0 = fmaxf(v0, 0.f); v1 = fmaxf(v1, 0.f);
                        v2 = fmaxf(v2, 0.f); v3 = fmaxf(v3, 0.f); }
            Cm[(size_t)(row0 + r) * Ccols + gc] = v0;
            Cm[(size_t)(row0 + r) * Ccols + gc + 1] = v1;
            Cm[(size_t)(row0 + r + 8) * Ccols + gc] = v2;
            Cm[(size_t)(row0 + r + 8) * Ccols + gc + 1] = v3;
        }
    }
}

// ================= fused persistent kernel =================
__device__ __forceinline__ void lbar2(int target) {
    __syncthreads();
    if (threadIdx.x == 0) {
        __threadfence();
        int g = blockIdx.x & 7;
        int old = atomicAdd(&g_grp[g * 32], 1);
        if (old == target * 8 - 1) {
            int mo = atomicAdd(&g_master[0], 1);
            if (mo == target * 8 - 1) {
                atomicExch(&g_release, target);
            }
        }
        while (*((volatile int*)&g_release) < target) __nanosleep(16);
        __threadfence();
    }
    __syncthreads();
}

__device__ void lstm_role(char* smc, const float* __restrict__ whh) {
    float* sm = (float*)smc;
    float* Wsl = sm;
    float* hs = sm + 16512;
    ull* part = (ull*)(sm + 20608);
    int tid = threadIdx.x;
    int m0 = blockIdx.x * 8;
    for (int i = tid; i < 32 * 512; i += 256) {
        int row = i >> 9, k = i & 511;
        int gate = row >> 3, ml = row & 7;
        Wsl[row * 516 + k] = whh[(gate * 512 + m0 + ml) * 512 + k];
    }
    if (tid < 64) __stcg(&g_hping[blockIdx.x * 64 + tid], 0.f);
    int w = tid >> 5, l = tid & 31;
    int g = w & 3;
    int khf = w >> 2;
    int k0 = khf * 256 + l;
    int ml_u = tid >> 3, b_u = tid & 7;
    float c_reg = 0.f;
    lbar2(1);
    for (int t = 0; t < Tt; t++) {
        int cur = t & 1, nxt = cur ^ 1;
        float gi0 = 0.f, gi1 = 0.f, gi2 = 0.f, gi3 = 0.f;
        if (tid < 64) {
            const float* gip = &g_GI[(t * 8 + b_u) * 2048 + m0 + ml_u];
            gi0 = __ldg(gip);
            gi1 = __ldg(gip + 512);
            gi2 = __ldg(gip + 1024);
            gi3 = __ldg(gip + 1536);
        }
        for (int i = tid; i < 2048; i += 256)
            ((float2*)hs)[i] = __ldcg(&((const float2*)g_hping)[cur * 2048 + i]);
        __syncthreads();
        ull acc[32];
#pragma unroll
        for (int i = 0; i < 32; i++) acc[i] = 0ull;
#pragma unroll
        for (int j = 0; j < 8; j++) {
            int k = k0 + 32 * j;
            ulonglong2 h01 = *(const ulonglong2*)&hs[k * 8];
            ulonglong2 h23 = *(const ulonglong2*)&hs[k * 8 + 4];
            ull hv0 = h01.x, hv1 = h01.y, hv2 = h23.x, hv3 = h23.y;
#pragma unroll
            for (int r = 0; r < 8; r++) {
                float wv = Wsl[(g * 8 + r) * 516 + k];
                ull wp;
                PACK2(wp, wv);
                FMA2(acc[r * 4 + 0], wp, hv0);
                FMA2(acc[r * 4 + 1], wp, hv1);
                FMA2(acc[r * 4 + 2], wp, hv2);
                FMA2(acc[r * 4 + 3], wp, hv3);
            }
        }
#define REDST(OFF, CNT)                                                    \
        {                                                                  \
            bool hib = (l & OFF) != 0;                                     \
            _Pragma("unroll")                                              \
            for (int i = 0; i < CNT; i++) {                                \
                ull snd = hib ? acc[i] : acc[i + CNT];                     \
                ull rcv = __shfl_xor_sync(0xffffffffu, snd, OFF);          \
                ull kp = hib ? acc[i + CNT] : acc[i];                      \
                ADD2(acc[i], kp, rcv);                                     \
            }                                                              \
        }
        REDST(16, 16) REDST(8, 8) REDST(4, 4) REDST(2, 2) REDST(1, 1)
#undef REDST
        part[w * 32 + l] = acc[0];
        __syncthreads();
        if (tid < 64) {
            int p = b_u >> 1, hi = b_u & 1;
            int L = ml_u * 4 + p;
            float gv[4];
#pragma unroll
            for (int gate = 0; gate < 4; gate++) {
                ull s;
                ADD2(s, part[gate * 32 + L], part[(gate + 4) * 32 + L]);
                float lo, hif;
                UNPK(lo, hif, s);
                gv[gate] = hi ? hif : lo;
            }
            float ig = gv[0] + gi0;
            float fg = gv[1] + gi1;
            float gg = gv[2] + gi2;
            float og = gv[3] + gi3;
            float cn = sigf(fg) * c_reg + sigf(ig) * tanhf(gg);
            float h = sigf(og) * tanhf(cn);
            c_reg = cn;
            __stcg(&g_hping[nxt * 4096 + (m0 + ml_u) * 8 + b_u], h);
            __stcg(&g_H[(t * 8 + b_u) * 512 + m0 + ml_u], h);
        }
        lbar2(t + 2);
    }
}

// batched HP + A1 precompute: one job per time-step t
__device__ void do_hp(char* smc, int t, const float* __restrict__ ob0) {
    float* Hs = (float*)smc;          // 8 x 512
    float* HPs = (float*)smc + 4096;  // 8 x 256
    int tid = threadIdx.x;
    for (int i = tid; i < 4096; i += 256)
        Hs[i] = __ldcg(&g_H[(size_t)t * 4096 + i]);
    __syncthreads();
    float a[8];
#pragma unroll
    for (int b = 0; b < 8; b++) a[b] = 0.f;
    const float* W = g_OW0MT;
    for (int m = 0; m < 512; m += 4) {
        float w0 = __ldg(&W[m * 256 + tid]);
        float w1 = __ldg(&W[(m + 1) * 256 + tid]);
        float w2 = __ldg(&W[(m + 2) * 256 + tid]);
        float w3 = __ldg(&W[(m + 3) * 256 + tid]);
#pragma unroll
        for (int b = 0; b < 8; b++) {
            float4 h4 = *(const float4*)&Hs[b * 512 + m];
            a[b] = fmaf(h4.x, w0, fmaf(h4.y, w1, fmaf(h4.z, w2, fmaf(h4.w, w3, a[b]))));
        }
    }
    float bb = ob0[tid];
#pragma unroll
    for (int b = 0; b < 8; b++) HPs[b * 256 + tid] = a[b] + bb;
    __syncthreads();
    // A1 = relu(ZI + HP) -> bf16 split -> global
    for (int i = tid; i < 8 * 128 * 128; i += 256) {
        int b = i >> 14;
        int rem = i & 16383;
        int r = rem >> 7;
        int kp = rem & 127;
        float2 z = *(const float2*)&g_ZI[(size_t)(b * 128 + r) * 256 + 2 * kp];
        float v0 = fmaxf(z.x + HPs[b * 256 + 2 * kp], 0.f);
        float v1 = fmaxf(z.y + HPs[b * 256 + 2 * kp + 1], 0.f);
        u32 hi, lo;
        bfsplit2(v0, v1, hi, lo);
        size_t dst = ((size_t)(t * 8 + b) * 128 + r) * 128 + kp;
        __stcg(&g_A1h[dst], hi);
        __stcg(&g_A1l[dst], lo);
    }
    __syncthreads();
    __threadfence();
    if (tid == 0) atomicExch(&g_hpdone[t], 1);
}

// g2: 2-term, all staging via cp.async
__device__ void do_g2(char* smc2, int tb, int half, const float* __restrict__ ob1) {
    u32 sbase = smem_to_u32(smc2);
    int col0 = half * 128;
    int tid = threadIdx.x;
    int warp = tid >> 5, lane = tid & 31;
    int wr = (warp & 3) * 32;
    int wc = (warp >> 2) * 64;
    float acc[2][8][4];
#pragma unroll
    for (int mt = 0; mt < 2; mt++)
#pragma unroll
        for (int nt = 0; nt < 8; nt++)
#pragma unroll
            for (int q = 0; q < 4; q++) acc[mt][nt][q] = 0.f;
    u32 lmrow = (u32)(lane & 15);
    u32 lmk = (u32)((lane >> 4) << 3);

    for (int kc = 0; kc < 4; kc++) {
        int kq = kc * 32;  // u32 offset in K/2
        // A: 128 rows x 8 16B units (hi + lo); B: 128 cols x 8 units
        for (int i = tid; i < 1024; i += 256) {
            int r = i >> 3, c = i & 7;
            u32 so = sbase + (u32)(r * 36 + c * 4) * 4;
            size_t gs = ((size_t)tb * 128 + r) * 128 + kq + c * 4;
            cpa16(so, &g_A1h[gs]);
            cpa16(so + 18432, &g_A1l[gs]);
            size_t gb = (size_t)(col0 + r) * 128 + kq + c * 4;
            cpa16(so + 36864, &((const u32*)g_B1h)[gb]);
        }
        cpa_commit();
        cpa_wait0();
        __syncthreads();
#pragma unroll
        for (int ks = 0; ks < 4; ks++) {
            u32 kk = (u32)(ks * 16);
            u32 a_h[2][4], a_l[2][4];
#pragma unroll
            for (int mt = 0; mt < 2; mt++) {
                u32 ad = sbase + (((u32)(wr + mt * 16) + lmrow) * 72 + kk + lmk) * 2;
                ldmx4(a_h[mt][0], a_h[mt][1], a_h[mt][2], a_h[mt][3], ad);
                ldmx4(a_l[mt][0], a_l[mt][1], a_l[mt][2], a_l[mt][3], ad + 18432);
            }
            u32 b_h[8][2];
#pragma unroll
            for (int np = 0; np < 4; np++) {
                u32 bd = sbase + 36864 +
                         (((u32)(wc + np * 16) + lmrow) * 72 + kk + lmk) * 2;
                u32 r0, r1, r2, r3;
                ldmx4(r0, r1, r2, r3, bd);
                b_h[np * 2][0] = r0; b_h[np * 2][1] = r2;
                b_h[np * 2 + 1][0] = r1; b_h[np * 2 + 1][1] = r3;
            }
#pragma unroll
            for (int mt = 0; mt < 2; mt++)
#pragma unroll
                for (int nt = 0; nt < 8; nt++) {
                    mma_bf16(acc[mt][nt], a_h[mt], b_h[nt]);
                    mma_bf16(acc[mt][nt], a_l[mt], b_h[nt]);
                }
        }
        __syncthreads();
    }
#pragma unroll
    for (int mt = 0; mt < 2; mt++) {
        int r = wr + mt * 16 + (lane >> 2);
#pragma unroll
        for (int nt = 0; nt < 8; nt++) {
            int col = wc + nt * 8 + (lane & 3) * 2;
            int gc = col0 + col;
            float bb0 = ob1[gc], bb1 = ob1[gc + 1];
            float v0 = fmaxf(acc[mt][nt][0] + bb0, 0.f);
            float v1 = fmaxf(acc[mt][nt][1] + bb1, 0.f);
            u32 hp, lp;
            bfsplit2(v0, v1, hp, lp);
            size_t dst = ((size_t)tb * 128 + r) * 128 + (gc >> 1);
            g_A2h[dst] = hp;
            g_A2l[dst] = lp;
            v0 = fmaxf(acc[mt][nt][2] + bb0, 0.f);
            v1 = fmaxf(acc[mt][nt][3] + bb1, 0.f);
            bfsplit2(v0, v1, hp, lp);
            dst = ((size_t)tb * 128 + r + 8) * 128 + (gc >> 1);
            g_A2h[dst] = hp;
            g_A2l[dst] = lp;
        }
    }
    __syncthreads();
    __threadfence();
    if (tid == 0) atomicAdd(&g_tbdone[tb], 1);
}

// g3: 2-term + emission epilogue, staging via cp.async
__device__ void do_g3(char* smc3, int tb, int nh, const float* __restrict__ mels) {
    u32 sbase = smem_to_u32(smc3);
    float* xt = (float*)(smc3 + 50688);
    float* redbuf = (float*)(smc3 + 51008);
    float* tvbuf = (float*)(smc3 + 52032);
    int col0 = nh * 96;
    int t = tb >> 3, b = tb & 7;
    int tid = threadIdx.x;
    int warp = tid >> 5, lane = tid & 31;
    int wr = (warp & 3) * 32;
    int wc = (warp >> 2) * 48;
    int cg = warp >> 2;
    if (tid < 80) xt[tid] = mels[(b * 80 + tid) * 256 + t];
    float acc[2][6][4];
#pragma unroll
    for (int mt = 0; mt < 2; mt++)
#pragma unroll
        for (int nt = 0; nt < 6; nt++)
#pragma unroll
            for (int q = 0; q < 4; q++) acc[mt][nt][q] = 0.f;
    u32 lmrow = (u32)(lane & 15);
    u32 lmk = (u32)((lane >> 4) << 3);

    for (int kc = 0; kc < 4; kc++) {
        int kq = kc * 32;
        for (int i = tid; i < 1024; i += 256) {
            int r = i >> 3, c = i & 7;
            u32 so = sbase + (u32)(r * 36 + c * 4) * 4;
            size_t gs = ((size_t)tb * 128 + r) * 128 + kq + c * 4;
            cpa16(so, &g_A2h[gs]);
            cpa16(so + 18432, &g_A2l[gs]);
        }
        for (int i = tid; i < 768; i += 256) {
            int n = i >> 3, c = i & 7;
            u32 so = sbase + 36864 + (u32)(n * 36 + c * 4) * 4;
            size_t gb = (size_t)(col0 + n) * 128 + kq + c * 4;
            cpa16(so, &((const u32*)g_B2h)[gb]);
        }
        cpa_commit();
        cpa_wait0();
        __syncthreads();
#pragma unroll
        for (int ks = 0; ks < 4; ks++) {
            u32 kk = (u32)(ks * 16);
            u32 a_h[2][4], a_l[2][4];
#pragma unroll
            for (int mt = 0; mt < 2; mt++) {
                u32 ad = sbase + (((u32)(wr + mt * 16) + lmrow) * 72 + kk + lmk) * 2;
                ldmx4(a_h[mt][0], a_h[mt][1], a_h[mt][2], a_h[mt][3], ad);
                ldmx4(a_l[mt][0], a_l[mt][1], a_l[mt][2], a_l[mt][3], ad + 18432);
            }
            u32 b_h[6][2];
#pragma unroll
            for (int np = 0; np < 3; np++) {
                u32 bd = sbase + 36864 +
                         (((u32)(wc + np * 16) + lmrow) * 72 + kk + lmk) * 2;
                u32 r0, r1, r2, r3;
                ldmx4(r0, r1, r2, r3, bd);
                b_h[np * 2][0] = r0; b_h[np * 2][1] = r2;
                b_h[np * 2 + 1][0] = r1; b_h[np * 2 + 1][1] = r3;
            }
#pragma unroll
            for (int mt = 0; mt < 2; mt++)
#pragma unroll
                for (int nt = 0; nt < 6; nt++) {
                    mma_bf16(acc[mt][nt], a_h[mt], b_h[nt]);
                    mma_bf16(acc[mt][nt], a_l[mt], b_h[nt]);
                }
        }
        __syncthreads();
    }
#pragma unroll
    for (int mt = 0; mt < 2; mt++) {
        int r = wr + mt * 16 + (lane >> 2);
        float em0 = 0.f, em1 = 0.f;
#pragma unroll
        for (int nt = 0; nt < 6; nt++) {
            int pcol = col0 + wc + nt * 8 + (lane & 3) * 2;
            if (pcol < 160) {
                float bb0 = g_ob2perm[pcol];
                float bb1 = g_ob2perm[pcol + 1];
                float x = xt[pcol >> 1];
                float m0 = acc[mt][nt][0] + bb0;
                float s0 = acc[mt][nt][1] + bb1;
                float sp0 = (s0 > 15.f) ? s0 : __logf(1.f + __expf(s0));
                float sd0 = sp0 + 0.001f;
                float z0 = (x - m0) / sd0;
                em0 += -0.5f * z0 * z0 - __logf(sd0);
                float m1 = acc[mt][nt][2] + bb0;
                float s1 = acc[mt][nt][3] + bb1;
                float sp1 = (s1 > 15.f) ? s1 : __logf(1.f + __expf(s1));
                float sd1 = sp1 + 0.001f;
                float z1 = (x - m1) / sd1;
                em1 += -0.5f * z1 * z1 - __logf(sd1);
            } else if (pcol == 160) {
                tvbuf[r] = acc[mt][nt][0] + g_ob2perm[160];
                tvbuf[r + 8] = acc[mt][nt][2] + g_ob2perm[160];
            }
        }
        em0 += __shfl_xor_sync(0xffffffffu, em0, 1);
        em0 += __shfl_xor_sync(0xffffffffu, em0, 2);
        em1 += __shfl_xor_sync(0xffffffffu, em1, 1);
        em1 += __shfl_xor_sync(0xffffffffu, em1, 2);
        if ((lane & 3) == 0) {
            redbuf[r * 2 + cg] = em0;
            redbuf[(r + 8) * 2 + cg] = em1;
        }
    }
    __syncthreads();
    if (tid < 128) {
        float em = redbuf[tid * 2] + redbuf[tid * 2 + 1];
        if (nh == 0) {
            g_EMa[(size_t)tb * 128 + tid] = em;
        } else {
            g_EMb[(size_t)tb * 128 + tid] = em;
            float tv = tvbuf[tid];
            float s_move = 1.f / (1.f + __expf(-tv));
            float s_stay = 1.f - s_move;
            g_LS[(size_t)tb * 128 + tid] = __logf(fmaxf(s_stay, EPSC));
            g_LM[(size_t)tb * 128 + tid] = __logf(fmaxf(s_move, EPSC));
        }
    }
    __syncthreads();
    __threadfence();
    if (tid == 0) atomicAdd(&g_emdone[t], 1);
}

// alpha as a resident role
__device__ void alpha_role(float* __restrict__ out, const int* __restrict__ inputs_len,
                           const int* __restrict__ mel_lens) {
    int tid = threadIdx.x;
    int b = tid >> 5, l = tid & 31;
    int ilen = inputs_len[b], mlen = mel_lens[b];
    float la[4];
    float lp = 0.f;
    bool mk[4];
#pragma unroll
    for (int j = 0; j < 4; j++) mk[j] = (l * 4 + j) < ilen;
    for (int t = 0; t < Tt; t++) {
        if (tid == 0) {
            while (*((volatile int*)&g_emdone[t]) < 16) __nanosleep(128);
        }
        __syncthreads();
        int base = ((t << 3) + b) * 128 + l * 4;
        float4 ea = __ldcg((const float4*)&g_EMa[base]);
        float4 eb = __ldcg((const float4*)&g_EMb[base]);
        float4 ls4 = __ldcg((const float4*)&g_LS[base]);
        float4 lm4 = __ldcg((const float4*)&g_LM[base]);
        float em[4];
        {
            float era[4] = {ea.x + eb.x, ea.y + eb.y, ea.z + eb.z, ea.w + eb.w};
#pragma unroll
            for (int j = 0; j < 4; j++)
                em[j] = mk[j] ? (era[j] - 40.f * LOG2PI) : 0.f;
        }
        float v[4];
        if (t == 0) {
#pragma unroll
            for (int j = 0; j < 4; j++)
                v[j] = ((l == 0 && j == 0) ? 0.f : NEGV) + em[j];
        } else {
            float lau = __shfl_up_sync(0xffffffffu, la[3], 1);
            float lmu = __shfl_up_sync(0xffffffffu, lm4.w, 1);
            float lam1[4] = {lau, la[0], la[1], la[2]};
            float lmm1[4] = {lmu, lm4.x, lm4.y, lm4.z};
            float ls[4] = {ls4.x, ls4.y, ls4.z, ls4.w};
#pragma unroll
            for (int j = 0; j < 4; j++) {
                float stay = la[j] + ls[j];
                float leave = (l == 0 && j == 0) ? NEGV : lam1[j] + lmm1[j];
                float mx = fmaxf(stay, leave), mn = fminf(stay, leave);
                float ladd = mx + __logf(1.f + __expf(mn - mx));
                v[j] = em[j] + (mk[j] ? ladd : NEGV);
            }
        }
        float m = fmaxf(fmaxf(v[0], v[1]), fmaxf(v[2], v[3]));
#pragma unroll
        for (int off = 16; off; off >>= 1)
            m = fmaxf(m, __shfl_xor_sync(0xffffffffu, m, off));
        float s = __expf(v[0] - m) + __expf(v[1] - m) +
                  __expf(v[2] - m) + __expf(v[3] - m);
#pragma unroll
        for (int off = 16; off; off >>= 1)
            s += __shfl_xor_sync(0xffffffffu, s, off);
        float logc = m + __logf(s);
#pragma unroll
        for (int j = 0; j < 4; j++) la[j] = v[j] - logc;
        *(float4*)&out[8 + ((b << 8) + t) * 128 + l * 4] =
            make_float4(la[0], la[1], la[2], la[3]);
        if (l == 0 && t < mlen) lp += logc;
    }
    if (l == 0) out[b] = lp;
}

__global__ __launch_bounds__(256, 2) void k_fused(const float* __restrict__ whh,
                                                  const float* __restrict__ mels,
                                                  const float* __restrict__ ob0,
                                                  const float* __restrict__ ob1,
                                                  float* __restrict__ out,
                                                  const int* __restrict__ inputs_len,
                                                  const int* __restrict__ mel_lens) {
    extern __shared__ __align__(16) char smc[];
    __shared__ int s_job;
    int tid = threadIdx.x;
    if (blockIdx.x < 64) {
        lstm_role(smc, whh);
    } else if (blockIdx.x == 64) {
        alpha_role(out, inputs_len, mel_lens);
    }
    for (;;) {
        __syncthreads();
        if (tid == 0) s_job = atomicAdd(&g_jobctr, 1);
        __syncthreads();
        int j = s_job;
        if (j >= NJOBS) break;
        int jt = j / 33;
        int r = j - jt * 33;
        if (r == 0) {
            if (tid == 0)
                while (*((volatile int*)&g_release) < jt + 2) __nanosleep(64);
            __syncthreads();
            __threadfence();
            do_hp(smc, jt, ob0);
        } else if (r < 17) {
            int rr = r - 1;
            int tb = jt * 8 + (rr >> 1);
            if (tid == 0)
                while (*((volatile int*)&g_hpdone[jt]) == 0) __nanosleep(64);
            __syncthreads();
            __threadfence();
            do_g2(smc, tb, rr & 1, ob1);
        } else {
            int rr = r - 17;
            int tb = jt * 8 + (rr >> 1);
            if (tid == 0)
                while (*((volatile int*)&g_tbdone[tb]) < 2) __nanosleep(64);
            __syncthreads();
            __threadfence();
            do_g3(smc, tb, rr & 1, mels);
        }
    }
}

// ---------------- launch ----------------
extern "C" void kernel_launch(void* const* d_in, const int* in_sizes, int n_in,
                              void* d_out, int out_size) {
    const float* inputs = (const float*)d_in[0];
    const float* mels = (const float*)d_in[1];
    const float* w0 = (const float*)d_in[2];
    const float* w1p = (const float*)d_in[3];
    const float* wih = (const float*)d_in[4];
    const float* whh = (const float*)d_in[5];
    const float* bih = (const float*)d_in[6];
    const float* bhh = (const float*)d_in[7];
    const float* ow0 = (const float*)d_in[8];
    const float* ob0 = (const float*)d_in[9];
    const float* ow1 = (const float*)d_in[10];
    const float* ob1 = (const float*)d_in[11];
    const float* ow2 = (const float*)d_in[12];
    const float* ob2 = (const float*)d_in[13];
    const int* inputs_len = (const int*)d_in[14];
    const int* mel_lens = (const int*)d_in[15];
    float* out = (float*)d_out;

    cudaFuncSetAttribute(k_fused, cudaFuncAttributeMaxDynamicSharedMemorySize,
                         FU_SMEMB);
    cudaFuncSetAttribute(k_hgemm<0>, cudaFuncAttributeMaxDynamicSharedMemorySize,
                         HG_SMEMB);
    cudaFuncSetAttribute(k_hgemm<1>, cudaFuncAttributeMaxDynamicSharedMemorySize,
                         HG_SMEMB);

    float* pre0;  cudaGetSymbolAddress((void**)&pre0, g_PRE0);
    float* pre;   cudaGetSymbolAddress((void**)&pre, g_PRE);
    float* gi;    cudaGetSymbolAddress((void**)&gi, g_GI);
    float* zi;    cudaGetSymbolAddress((void**)&zi, g_ZI);
    float* arx;   cudaGetSymbolAddress((void**)&arx, g_ARX);
    float* w0t;   cudaGetSymbolAddress((void**)&w0t, g_W0T);
    float* bsum;  cudaGetSymbolAddress((void**)&bsum, g_bsum);
    u32* w1h;  cudaGetSymbolAddress((void**)&w1h, g_W1sp_h);
    u32* w1l;  cudaGetSymbolAddress((void**)&w1l, g_W1sp_l);
    u32* wihh; cudaGetSymbolAddress((void**)&wihh, g_WIHsp_h);
    u32* wihl; cudaGetSymbolAddress((void**)&wihl, g_WIHsp_l);
    u32* oeh;  cudaGetSymbolAddress((void**)&oeh, g_OW0Esp_h);
    u32* oel;  cudaGetSymbolAddress((void**)&oel, g_OW0Esp_l);

    k_prep<<<256, 256>>>(w0, w1p, wih, ow0, ow1, ow2, ob2, bih, bhh, mels);
    k_gemm<1><<<dim3(2, 32), 256>>>(pre0, arx, w0t, nullptr, 2048, 256, 96);
    k_hgemm<1><<<dim3(2, 16), 256, HG_SMEMB>>>(pre, pre0, w1h, w1l, nullptr, 256, 256);
    k_hgemm<0><<<dim3(16, 16), 256, HG_SMEMB>>>(gi, pre, wihh, wihl, bsum, 2048, 256);
    k_hgemm<0><<<dim3(2, 8), 256, HG_SMEMB>>>(zi, inputs, oeh, oel, nullptr, 256, 512);
    k_fused<<<296, 256, FU_SMEMB>>>(whh, mels, ob0, ob1, out, inputs_len, mel_lens);
    (void)in_sizes; (void)n_in; (void)out_size;
}

// round 16
// speedup vs baseline: 2.4588x; 2.4588x over previous
#include <cuda_runtime.h>
#include <cstdint>
#include <math.h>

#define Tt 256
#define NEGV -1e10f
#define EPSC 1e-4f
#define LOG2PI 1.8378770664093453f
#define NJOBS 8448
#define FU_SMEMB 84480

typedef unsigned long long ull;
typedef unsigned int u32;

#define PACK2(out, x) asm("mov.b64 %0, {%1, %1};" : "=l"(out) : "r"(__float_as_uint(x)))
#define UNPK(lo, hi, in) { unsigned int ulo, uhi; \
    asm("mov.b64 {%0, %1}, %2;" : "=r"(ulo), "=r"(uhi) : "l"(in)); \
    lo = __uint_as_float(ulo); hi = __uint_as_float(uhi); }
#define FMA2(d, a, b) asm("fma.rn.f32x2 %0, %1, %2, %0;" : "+l"(d) : "l"(a), "l"(b))
#define ADD2(d, a, b) asm("add.rn.f32x2 %0, %1, %2;" : "=l"(d) : "l"(a), "l"(b))

__device__ __forceinline__ u32 bf16_bits(float a) {
    u32 u = __float_as_uint(a);
    return (u + 0x7FFFu + ((u >> 16) & 1u)) >> 16;
}
// rounding split (used in prep only)
__device__ __forceinline__ void bfsplit2(float a0, float a1, u32& hi, u32& lo) {
    u32 h0 = bf16_bits(a0);
    u32 h1 = bf16_bits(a1);
    float h0f = __uint_as_float(h0 << 16);
    float h1f = __uint_as_float(h1 << 16);
    u32 l0 = bf16_bits(a0 - h0f);
    u32 l1 = bf16_bits(a1 - h1f);
    hi = (h1 << 16) | h0;
    lo = (l1 << 16) | l0;
}
// truncation split (hot path): hi = trunc bf16, lo = trunc bf16 of residual
__device__ __forceinline__ void bfsplit2t(float a0, float a1, u32& hi, u32& lo) {
    u32 u0 = __float_as_uint(a0);
    u32 u1 = __float_as_uint(a1);
    float r0 = a0 - __uint_as_float(u0 & 0xFFFF0000u);
    float r1 = a1 - __uint_as_float(u1 & 0xFFFF0000u);
    hi = (u1 & 0xFFFF0000u) | (u0 >> 16);
    lo = (__float_as_uint(r1) & 0xFFFF0000u) | (__float_as_uint(r0) >> 16);
}
__device__ __forceinline__ u32 smem_to_u32(const void* p) {
    u32 a;
    asm("{ .reg .u64 t; cvta.to.shared.u64 t, %1; cvt.u32.u64 %0, t; }"
        : "=r"(a) : "l"(p));
    return a;
}
__device__ __forceinline__ void ldmx4(u32& r0, u32& r1, u32& r2, u32& r3, u32 addr) {
    asm volatile("ldmatrix.sync.aligned.m8n8.x4.shared.b16 {%0,%1,%2,%3}, [%4];"
                 : "=r"(r0), "=r"(r1), "=r"(r2), "=r"(r3) : "r"(addr));
}
__device__ __forceinline__ void mma_bf16(float* c, const u32* a, const u32* b) {
    asm volatile("mma.sync.aligned.m16n8k16.row.col.f32.bf16.bf16.f32 "
                 "{%0,%1,%2,%3}, {%4,%5,%6,%7}, {%8,%9}, {%0,%1,%2,%3};"
                 : "+f"(c[0]), "+f"(c[1]), "+f"(c[2]), "+f"(c[3])
                 : "r"(a[0]), "r"(a[1]), "r"(a[2]), "r"(a[3]),
                   "r"(b[0]), "r"(b[1]));
}

// ---------------- device scratch ----------------
__device__ float g_W0T[96 * 256];
__device__ float g_bsum[2048];
__device__ float g_ARX[2048 * 96];
__device__ float g_PRE0[2048 * 256];
__device__ float g_PRE[2048 * 256];
__device__ float g_GI[2048 * 2048];
__device__ float g_ZI[1024 * 256];
__device__ float g_H[2048 * 512];
__device__ float g_HP[2048 * 256];
__device__ float g_OW0MT[512 * 256];
__device__ float g_hping[2 * 4096];
__device__ float g_EMa[2048 * 128];
__device__ float g_EMb[2048 * 128];
__device__ float g_LS[2048 * 128];
__device__ float g_LM[2048 * 128];
__device__ float g_ob2perm[192];
__device__ u32 g_W1sp_h[256 * 128];
__device__ u32 g_W1sp_l[256 * 128];
__device__ u32 g_WIHsp_h[2048 * 128];
__device__ u32 g_WIHsp_l[2048 * 128];
__device__ u32 g_OW0Esp_h[256 * 256];
__device__ u32 g_OW0Esp_l[256 * 256];
__device__ unsigned short g_B1h[256 * 256];
__device__ unsigned short g_B2h[192 * 256];
__device__ u32 g_A2h[(size_t)2048 * 128 * 128];
__device__ u32 g_A2l[(size_t)2048 * 128 * 128];
__device__ int g_grp[8 * 32];
__device__ int g_master[32];
__device__ int g_release;
__device__ int g_jobctr;
__device__ int g_hpdone[256];
__device__ int g_tbdone[2048];
__device__ int g_emdone[256];

__device__ __forceinline__ float sigf(float x) { return 1.f / (1.f + __expf(-x)); }

// ---------------- prep ----------------
__global__ void k_prep(const float* __restrict__ w0, const float* __restrict__ w1p,
                       const float* __restrict__ wih, const float* __restrict__ ow0,
                       const float* __restrict__ ow1, const float* __restrict__ ow2,
                       const float* __restrict__ ob2, const float* __restrict__ bih,
                       const float* __restrict__ bhh, const float* __restrict__ mels) {
    int stride = gridDim.x * blockDim.x;
    int t0 = blockIdx.x * blockDim.x + threadIdx.x;
    for (int i = t0; i < 96 * 256; i += stride) {
        int k = i >> 8, p = i & 255;
        g_W0T[i] = (k < 80) ? w0[p * 80 + k] : 0.f;
    }
    for (int i = t0; i < 2048; i += stride) g_bsum[i] = bih[i] + bhh[i];
    for (int i = t0; i < 2048 * 96; i += stride) {
        int row = i / 96, d = i % 96;
        int t = row >> 3, b = row & 7;
        g_ARX[i] = (d < 80 && t > 0) ? mels[(b * 80 + d) * 256 + (t - 1)] : 0.f;
    }
    if (t0 < 8 * 32) g_grp[t0] = 0;
    if (t0 < 32) g_master[t0] = 0;
    if (t0 == 0) { g_release = 0; g_jobctr = 0; }
    if (t0 < 256) { g_hpdone[t0] = 0; g_emdone[t0] = 0; }
    for (int i = t0; i < 2048; i += stride) g_tbdone[i] = 0;
    for (int i = t0; i < 256 * 128; i += stride) {
        int n = i >> 7, kp = i & 127;
        u32 hi, lo;
        bfsplit2(w1p[n * 256 + 2 * kp], w1p[n * 256 + 2 * kp + 1], hi, lo);
        g_W1sp_h[i] = hi; g_W1sp_l[i] = lo;
    }
    for (int i = t0; i < 2048 * 128; i += stride) {
        int n = i >> 7, kp = i & 127;
        u32 hi, lo;
        bfsplit2(wih[n * 256 + 2 * kp], wih[n * 256 + 2 * kp + 1], hi, lo);
        g_WIHsp_h[i] = hi; g_WIHsp_l[i] = lo;
    }
    for (int i = t0; i < 256 * 256; i += stride) {
        int n = i >> 8, kp = i & 255;
        u32 hi, lo;
        bfsplit2(ow0[n * 1024 + 2 * kp], ow0[n * 1024 + 2 * kp + 1], hi, lo);
        g_OW0Esp_h[i] = hi; g_OW0Esp_l[i] = lo;
    }
    for (int i = t0; i < 512 * 256; i += stride) {
        int m = i >> 8, n = i & 255;
        g_OW0MT[i] = ow0[n * 1024 + 512 + m];
    }
    for (int i = t0; i < 65536; i += stride)
        g_B1h[i] = (unsigned short)bf16_bits(ow1[i]);
    for (int i = t0; i < 192 * 256; i += stride) {
        int n = i >> 8, k = i & 255;
        float w = 0.f;
        if (n < 160) {
            int sf = (n & 1) ? (80 + (n >> 1)) : (n >> 1);
            w = ow2[sf * 256 + k];
        } else if (n == 160) {
            w = ow2[160 * 256 + k];
        }
        g_B2h[i] = (unsigned short)bf16_bits(w);
    }
    for (int i = t0; i < 192; i += stride) {
        float v = 0.f;
        if (i < 160) v = ob2[(i & 1) ? (80 + (i >> 1)) : (i >> 1)];
        else if (i == 160) v = ob2[160];
        g_ob2perm[i] = v;
    }
}

// ---------------- f32x2 SGEMM (PRE0 only) ----------------
template <int ACT>
__global__ __launch_bounds__(256) void k_gemm(float* __restrict__ Cm,
                                              const float* __restrict__ Am,
                                              const float* __restrict__ BT,
                                              const float* __restrict__ bias,
                                              int R, int Ccols, int K) {
    __shared__ __align__(16) float As[32 * 68];
    __shared__ __align__(16) float Bs[32 * 128];
    int row0 = blockIdx.y * 64, col0 = blockIdx.x * 128;
    int tid = threadIdx.x;
    int tr = tid >> 4, tc = tid & 15;
    int r0 = tr * 4, c0 = tc * 8;
    ull acc0[8], acc1[8];
#pragma unroll
    for (int c = 0; c < 8; c++) { acc0[c] = 0ull; acc1[c] = 0ull; }
    for (int kt = 0; kt < K; kt += 32) {
        for (int i = tid; i < 2048; i += 256) {
            int r = i >> 5, k = i & 31;
            As[k * 68 + r] = Am[(row0 + r) * K + kt + k];
        }
        for (int i = tid; i < 4096; i += 256) {
            int k = i >> 7, c = i & 127;
            Bs[k * 128 + c] = BT[(kt + k) * Ccols + col0 + c];
        }
        __syncthreads();
#pragma unroll 8
        for (int k = 0; k < 32; k++) {
            ulonglong2 ap = *(const ulonglong2*)&As[k * 68 + r0];
            float4 b0 = *(const float4*)&Bs[k * 128 + c0];
            float4 b1 = *(const float4*)&Bs[k * 128 + c0 + 4];
            float wf[8] = {b0.x, b0.y, b0.z, b0.w, b1.x, b1.y, b1.z, b1.w};
#pragma unroll
            for (int c = 0; c < 8; c++) {
                ull wp;
                PACK2(wp, wf[c]);
                FMA2(acc0[c], ap.x, wp);
                FMA2(acc1[c], ap.y, wp);
            }
        }
        __syncthreads();
    }
#pragma unroll
    for (int c = 0; c < 8; c++) {
        int cc = col0 + c0 + c;
        float bb = bias ? bias[cc] : 0.f;
        float v0, v1, v2, v3;
        UNPK(v0, v1, acc0[c]);
        UNPK(v2, v3, acc1[c]);
        v0 += bb; v1 += bb; v2 += bb; v3 += bb;
        if (ACT) { v0 = fmaxf(v0, 0.f); v1 = fmaxf(v1, 0.f);
                   v2 = fmaxf(v2, 0.f); v3 = fmaxf(v3, 0.f); }
        Cm[(row0 + r0 + 0) * Ccols + cc] = v0;
        Cm[(row0 + r0 + 1) * Ccols + cc] = v1;
        Cm[(row0 + r0 + 2) * Ccols + cc] = v2;
        Cm[(row0 + r0 + 3) * Ccols + cc] = v3;
    }
}

// ---------------- generic HMMA GEMM (PRE, GI, ZI; 3-term) ----------------
#define HG_SMEMB 73728

template <int RELU>
__global__ __launch_bounds__(256, 1) void k_hgemm(float* __restrict__ Cm,
                                                  const float* __restrict__ Am,
                                                  const u32* __restrict__ Bh,
                                                  const u32* __restrict__ Bl,
                                                  const float* __restrict__ bias,
                                                  int Ccols, int K) {
    extern __shared__ __align__(16) char smh[];
    u32 sbase = smem_to_u32(smh);
    u32* Ah32 = (u32*)smh;
    u32* Al32 = (u32*)(smh + 18432);
    u32* Bh32 = (u32*)(smh + 36864);
    u32* Bl32 = (u32*)(smh + 55296);
    int row0 = blockIdx.y * 128, col0 = blockIdx.x * 128;
    int tid = threadIdx.x;
    int warp = tid >> 5, lane = tid & 31;
    int wr = (warp & 3) * 32;
    int wc = (warp >> 2) * 64;
    int Kh = K >> 1;
    float acc[2][8][4];
#pragma unroll
    for (int mt = 0; mt < 2; mt++)
#pragma unroll
        for (int nt = 0; nt < 8; nt++)
#pragma unroll
            for (int q = 0; q < 4; q++) acc[mt][nt][q] = 0.f;
    u32 lmrow = (u32)(lane & 15);
    u32 lmk = (u32)((lane >> 4) << 3);

    for (int kc = 0; kc < (K >> 6); kc++) {
        int k0 = kc * 64;
        for (int i = tid; i < 4096; i += 256) {
            int r = i >> 5, kp = i & 31;
            float2 av = *(const float2*)&Am[(size_t)(row0 + r) * K + k0 + 2 * kp];
            u32 hi, lo;
            bfsplit2t(av.x, av.y, hi, lo);
            Ah32[r * 36 + kp] = hi;
            Al32[r * 36 + kp] = lo;
        }
        for (int i = tid; i < 4096; i += 256) {
            int n = i >> 5, kp = i & 31;
            size_t gsrc = (size_t)(col0 + n) * Kh + (k0 >> 1) + kp;
            Bh32[n * 36 + kp] = Bh[gsrc];
            Bl32[n * 36 + kp] = Bl[gsrc];
        }
        __syncthreads();
#pragma unroll
        for (int ks = 0; ks < 4; ks++) {
            u32 kk = (u32)(ks * 16);
            u32 a_h[2][4], a_l[2][4];
#pragma unroll
            for (int mt = 0; mt < 2; mt++) {
                u32 ad = sbase + (((u32)(wr + mt * 16) + lmrow) * 72 + kk + lmk) * 2;
                ldmx4(a_h[mt][0], a_h[mt][1], a_h[mt][2], a_h[mt][3], ad);
                ldmx4(a_l[mt][0], a_l[mt][1], a_l[mt][2], a_l[mt][3], ad + 18432);
            }
            u32 b_h[8][2], b_l[8][2];
#pragma unroll
            for (int np = 0; np < 4; np++) {
                u32 bd = sbase + 36864 +
                         (((u32)(wc + np * 16) + lmrow) * 72 + kk + lmk) * 2;
                u32 r0, r1, r2, r3;
                ldmx4(r0, r1, r2, r3, bd);
                b_h[np * 2][0] = r0; b_h[np * 2][1] = r2;
                b_h[np * 2 + 1][0] = r1; b_h[np * 2 + 1][1] = r3;
                ldmx4(r0, r1, r2, r3, bd + 18432);
                b_l[np * 2][0] = r0; b_l[np * 2][1] = r2;
                b_l[np * 2 + 1][0] = r1; b_l[np * 2 + 1][1] = r3;
            }
#pragma unroll
            for (int mt = 0; mt < 2; mt++)
#pragma unroll
                for (int nt = 0; nt < 8; nt++) {
                    mma_bf16(acc[mt][nt], a_h[mt], b_h[nt]);
                    mma_bf16(acc[mt][nt], a_l[mt], b_h[nt]);
                    mma_bf16(acc[mt][nt], a_h[mt], b_l[nt]);
                }
        }
        __syncthreads();
    }
#pragma unroll
    for (int mt = 0; mt < 2; mt++) {
        int r = wr + mt * 16 + (lane >> 2);
#pragma unroll
        for (int nt = 0; nt < 8; nt++) {
            int gc = col0 + wc + nt * 8 + (lane & 3) * 2;
            float bb0 = bias ? bias[gc] : 0.f;
            float bb1 = bias ? bias[gc + 1] : 0.f;
            float v0 = acc[mt][nt][0] + bb0;
            float v1 = acc[mt][nt][1] + bb1;
            float v2 = acc[mt][nt][2] + bb0;
            float v3 = acc[mt][nt][3] + bb1;
            if (RELU) { v0 = fmaxf(v0, 0.f); v1 = fmaxf(v1, 0.f);
                        v2 = fmaxf(v2, 0.f); v3 = fmaxf(v3, 0.f); }
            Cm[(size_t)(row0 + r) * Ccols + gc] = v0;
            Cm[(size_t)(row0 + r) * Ccols + gc + 1] = v1;
            Cm[(size_t)(row0 + r + 8) * Ccols + gc] = v2;
            Cm[(size_t)(row0 + r + 8) * Ccols + gc + 1] = v3;
        }
    }
}

// ================= fused persistent kernel =================
__device__ __forceinline__ void lbar2(int target) {
    __syncthreads();
    if (threadIdx.x == 0) {
        __threadfence();
        int g = blockIdx.x & 7;
        int old = atomicAdd(&g_grp[g * 32], 1);
        if (old == target * 8 - 1) {
            int mo = atomicAdd(&g_master[0], 1);
            if (mo == target * 8 - 1) {
                atomicExch(&g_release, target);
            }
        }
        while (*((volatile int*)&g_release) < target) __nanosleep(16);
        __threadfence();
    }
    __syncthreads();
}

__device__ void lstm_role(char* smc, const float* __restrict__ whh) {
    float* sm = (float*)smc;
    float* Wsl = sm;
    float* hs = sm + 16512;
    ull* part = (ull*)(sm + 20608);
    int tid = threadIdx.x;
    int m0 = blockIdx.x * 8;
    for (int i = tid; i < 32 * 512; i += 256) {
        int row = i >> 9, k = i & 511;
        int gate = row >> 3, ml = row & 7;
        Wsl[row * 516 + k] = whh[(gate * 512 + m0 + ml) * 512 + k];
    }
    if (tid < 64) __stcg(&g_hping[blockIdx.x * 64 + tid], 0.f);
    int w = tid >> 5, l = tid & 31;
    int g = w & 3;
    int khf = w >> 2;
    int k0 = khf * 256 + l;
    int ml_u = tid >> 3, b_u = tid & 7;
    float c_reg = 0.f;
    lbar2(1);
    for (int t = 0; t < Tt; t++) {
        int cur = t & 1, nxt = cur ^ 1;
        float gi0 = 0.f, gi1 = 0.f, gi2 = 0.f, gi3 = 0.f;
        if (tid < 64) {
            const float* gip = &g_GI[(t * 8 + b_u) * 2048 + m0 + ml_u];
            gi0 = __ldg(gip);
            gi1 = __ldg(gip + 512);
            gi2 = __ldg(gip + 1024);
            gi3 = __ldg(gip + 1536);
        }
        for (int i = tid; i < 2048; i += 256)
            ((float2*)hs)[i] = __ldcg(&((const float2*)g_hping)[cur * 2048 + i]);
        __syncthreads();
        ull acc[32];
#pragma unroll
        for (int i = 0; i < 32; i++) acc[i] = 0ull;
#pragma unroll
        for (int j = 0; j < 8; j++) {
            int k = k0 + 32 * j;
            ulonglong2 h01 = *(const ulonglong2*)&hs[k * 8];
            ulonglong2 h23 = *(const ulonglong2*)&hs[k * 8 + 4];
            ull hv0 = h01.x, hv1 = h01.y, hv2 = h23.x, hv3 = h23.y;
#pragma unroll
            for (int r = 0; r < 8; r++) {
                float wv = Wsl[(g * 8 + r) * 516 + k];
                ull wp;
                PACK2(wp, wv);
                FMA2(acc[r * 4 + 0], wp, hv0);
                FMA2(acc[r * 4 + 1], wp, hv1);
                FMA2(acc[r * 4 + 2], wp, hv2);
                FMA2(acc[r * 4 + 3], wp, hv3);
            }
        }
#define REDST(OFF, CNT)                                                    \
        {                                                                  \
            bool hib = (l & OFF) != 0;                                     \
            _Pragma("unroll")                                              \
            for (int i = 0; i < CNT; i++) {                                \
                ull snd = hib ? acc[i] : acc[i + CNT];                     \
                ull rcv = __shfl_xor_sync(0xffffffffu, snd, OFF);          \
                ull kp = hib ? acc[i + CNT] : acc[i];                      \
                ADD2(acc[i], kp, rcv);                                     \
            }                                                              \
        }
        REDST(16, 16) REDST(8, 8) REDST(4, 4) REDST(2, 2) REDST(1, 1)
#undef REDST
        part[w * 32 + l] = acc[0];
        __syncthreads();
        if (tid < 64) {
            int p = b_u >> 1, hi = b_u & 1;
            int L = ml_u * 4 + p;
            float gv[4];
#pragma unroll
            for (int gate = 0; gate < 4; gate++) {
                ull s;
                ADD2(s, part[gate * 32 + L], part[(gate + 4) * 32 + L]);
                float lo, hif;
                UNPK(lo, hif, s);
                gv[gate] = hi ? hif : lo;
            }
            float ig = gv[0] + gi0;
            float fg = gv[1] + gi1;
            float gg = gv[2] + gi2;
            float og = gv[3] + gi3;
            float cn = sigf(fg) * c_reg + sigf(ig) * tanhf(gg);
            float h = sigf(og) * tanhf(cn);
            c_reg = cn;
            __stcg(&g_hping[nxt * 4096 + (m0 + ml_u) * 8 + b_u], h);
            __stcg(&g_H[(t * 8 + b_u) * 512 + m0 + ml_u], h);
        }
        lbar2(t + 2);
    }
}

// batched HP: one job computes HP for all 8 b of time-step t
__device__ void do_hp(char* smc, int t, const float* __restrict__ ob0) {
    float* Hs = (float*)smc;
    int tid = threadIdx.x;
    for (int i = tid; i < 4096; i += 256)
        Hs[i] = __ldcg(&g_H[(size_t)t * 4096 + i]);
    __syncthreads();
    float a[8];
#pragma unroll
    for (int b = 0; b < 8; b++) a[b] = 0.f;
    const float* W = g_OW0MT;
    for (int m = 0; m < 512; m += 4) {
        float w0 = __ldg(&W[m * 256 + tid]);
        float w1 = __ldg(&W[(m + 1) * 256 + tid]);
        float w2 = __ldg(&W[(m + 2) * 256 + tid]);
        float w3 = __ldg(&W[(m + 3) * 256 + tid]);
#pragma unroll
        for (int b = 0; b < 8; b++) {
            float4 h4 = *(const float4*)&Hs[b * 512 + m];
            a[b] = fmaf(h4.x, w0, fmaf(h4.y, w1, fmaf(h4.z, w2, fmaf(h4.w, w3, a[b]))));
        }
    }
    float bb = ob0[tid];
#pragma unroll
    for (int b = 0; b < 8; b++)
        g_HP[(size_t)(t * 8 + b) * 256 + tid] = a[b] + bb;
    __syncthreads();
    __threadfence();
    if (tid == 0) atomicExch(&g_hpdone[t], 1);
}

// g2: 2-term (drop weights-lo)
__device__ void do_g2(char* smc2, int tb, int half, const float* __restrict__ ob1) {
    u32 sbase = smem_to_u32(smc2);
    u32* Ah32 = (u32*)smc2;
    u32* Al32 = (u32*)(smc2 + 18432);
    u32* Bh32 = (u32*)(smc2 + 36864);
    int col0 = half * 128;
    int b = tb & 7;
    int tid = threadIdx.x;
    int warp = tid >> 5, lane = tid & 31;
    int wr = (warp & 3) * 32;
    int wc = (warp >> 2) * 64;
    float acc[2][8][4];
#pragma unroll
    for (int mt = 0; mt < 2; mt++)
#pragma unroll
        for (int nt = 0; nt < 8; nt++)
#pragma unroll
            for (int q = 0; q < 4; q++) acc[mt][nt][q] = 0.f;
    const u32* gB1h = (const u32*)g_B1h;
    u32 lmrow = (u32)(lane & 15);
    u32 lmk = (u32)((lane >> 4) << 3);

    for (int kc = 0; kc < 4; kc++) {
        int k0 = kc * 64;
        for (int i = tid; i < 4096; i += 256) {
            int r = i >> 5, kp = i & 31;
            float2 za = *(const float2*)&g_ZI[(size_t)(b * 128 + r) * 256 + k0 + 2 * kp];
            float2 hp = __ldcg((const float2*)&g_HP[(size_t)tb * 256 + k0 + 2 * kp]);
            float a0 = fmaxf(za.x + hp.x, 0.f);
            float a1 = fmaxf(za.y + hp.y, 0.f);
            u32 hi, lo;
            bfsplit2t(a0, a1, hi, lo);
            Ah32[r * 36 + kp] = hi;
            Al32[r * 36 + kp] = lo;
        }
        for (int i = tid; i < 4096; i += 256) {
            int n = i >> 5, kp = i & 31;
            size_t gsrc = (size_t)(col0 + n) * 128 + (k0 >> 1) + kp;
            Bh32[n * 36 + kp] = gB1h[gsrc];
        }
        __syncthreads();
#pragma unroll
        for (int ks = 0; ks < 4; ks++) {
            u32 kk = (u32)(ks * 16);
            u32 a_h[2][4], a_l[2][4];
#pragma unroll
            for (int mt = 0; mt < 2; mt++) {
                u32 ad = sbase + (((u32)(wr + mt * 16) + lmrow) * 72 + kk + lmk) * 2;
                ldmx4(a_h[mt][0], a_h[mt][1], a_h[mt][2], a_h[mt][3], ad);
                ldmx4(a_l[mt][0], a_l[mt][1], a_l[mt][2], a_l[mt][3], ad + 18432);
            }
            u32 b_h[8][2];
#pragma unroll
            for (int np = 0; np < 4; np++) {
                u32 bd = sbase + 36864 +
                         (((u32)(wc + np * 16) + lmrow) * 72 + kk + lmk) * 2;
                u32 r0, r1, r2, r3;
                ldmx4(r0, r1, r2, r3, bd);
                b_h[np * 2][0] = r0; b_h[np * 2][1] = r2;
                b_h[np * 2 + 1][0] = r1; b_h[np * 2 + 1][1] = r3;
            }
#pragma unroll
            for (int mt = 0; mt < 2; mt++)
#pragma unroll
                for (int nt = 0; nt < 8; nt++) {
                    mma_bf16(acc[mt][nt], a_h[mt], b_h[nt]);
                    mma_bf16(acc[mt][nt], a_l[mt], b_h[nt]);
                }
        }
        __syncthreads();
    }
#pragma unroll
    for (int mt = 0; mt < 2; mt++) {
        int r = wr + mt * 16 + (lane >> 2);
#pragma unroll
        for (int nt = 0; nt < 8; nt++) {
            int col = wc + nt * 8 + (lane & 3) * 2;
            int gc = col0 + col;
            float bb0 = ob1[gc], bb1 = ob1[gc + 1];
            float v0 = fmaxf(acc[mt][nt][0] + bb0, 0.f);
            float v1 = fmaxf(acc[mt][nt][1] + bb1, 0.f);
            u32 hp, lp;
            bfsplit2t(v0, v1, hp, lp);
            size_t dst = ((size_t)tb * 128 + r) * 128 + (gc >> 1);
            g_A2h[dst] = hp;
            g_A2l[dst] = lp;
            v0 = fmaxf(acc[mt][nt][2] + bb0, 0.f);
            v1 = fmaxf(acc[mt][nt][3] + bb1, 0.f);
            bfsplit2t(v0, v1, hp, lp);
            dst = ((size_t)tb * 128 + r + 8) * 128 + (gc >> 1);
            g_A2h[dst] = hp;
            g_A2l[dst] = lp;
        }
    }
    __syncthreads();
    __threadfence();
    if (tid == 0) atomicAdd(&g_tbdone[tb], 1);
}

// g3: 2-term + emission epilogue
__device__ void do_g3(char* smc3, int tb, int nh, const float* __restrict__ mels) {
    u32 sbase = smem_to_u32(smc3);
    u32* Ah32 = (u32*)smc3;
    u32* Al32 = (u32*)(smc3 + 18432);
    u32* Bh32 = (u32*)(smc3 + 36864);
    float* xt = (float*)(smc3 + 50688);
    float* redbuf = (float*)(smc3 + 51008);
    float* tvbuf = (float*)(smc3 + 52032);
    int col0 = nh * 96;
    int t = tb >> 3, b = tb & 7;
    int tid = threadIdx.x;
    int warp = tid >> 5, lane = tid & 31;
    int wr = (warp & 3) * 32;
    int wc = (warp >> 2) * 48;
    int cg = warp >> 2;
    if (tid < 80) xt[tid] = mels[(b * 80 + tid) * 256 + t];
    float acc[2][6][4];
#pragma unroll
    for (int mt = 0; mt < 2; mt++)
#pragma unroll
        for (int nt = 0; nt < 6; nt++)
#pragma unroll
            for (int q = 0; q < 4; q++) acc[mt][nt][q] = 0.f;
    const u32* gB2h = (const u32*)g_B2h;
    u32 lmrow = (u32)(lane & 15);
    u32 lmk = (u32)((lane >> 4) << 3);

    for (int kc = 0; kc < 4; kc++) {
        int k0 = kc * 64;
        for (int i = tid; i < 4096; i += 256) {
            int r = i >> 5, kp = i & 31;
            size_t gsrc = ((size_t)tb * 128 + r) * 128 + (k0 >> 1) + kp;
            Ah32[r * 36 + kp] = __ldcg(&g_A2h[gsrc]);
            Al32[r * 36 + kp] = __ldcg(&g_A2l[gsrc]);
        }
        for (int i = tid; i < 3072; i += 256) {
            int n = i >> 5, kp = i & 31;
            size_t gsrc = (size_t)(col0 + n) * 128 + (k0 >> 1) + kp;
            Bh32[n * 36 + kp] = gB2h[gsrc];
        }
        __syncthreads();
#pragma unroll
        for (int ks = 0; ks < 4; ks++) {
            u32 kk = (u32)(ks * 16);
            u32 a_h[2][4], a_l[2][4];
#pragma unroll
            for (int mt = 0; mt < 2; mt++) {
                u32 ad = sbase + (((u32)(wr + mt * 16) + lmrow) * 72 + kk + lmk) * 2;
                ldmx4(a_h[mt][0], a_h[mt][1], a_h[mt][2], a_h[mt][3], ad);
                ldmx4(a_l[mt][0], a_l[mt][1], a_l[mt][2], a_l[mt][3], ad + 18432);
            }
            u32 b_h[6][2];
#pragma unroll
            for (int np = 0; np < 3; np++) {
                u32 bd = sbase + 36864 +
                         (((u32)(wc + np * 16) + lmrow) * 72 + kk + lmk) * 2;
                u32 r0, r1, r2, r3;
                ldmx4(r0, r1, r2, r3, bd);
                b_h[np * 2][0] = r0; b_h[np * 2][1] = r2;
                b_h[np * 2 + 1][0] = r1; b_h[np * 2 + 1][1] = r3;
            }
#pragma unroll
            for (int mt = 0; mt < 2; mt++)
#pragma unroll
                for (int nt = 0; nt < 6; nt++) {
                    mma_bf16(acc[mt][nt], a_h[mt], b_h[nt]);
                    mma_bf16(acc[mt][nt], a_l[mt], b_h[nt]);
                }
        }
        __syncthreads();
    }
#pragma unroll
    for (int mt = 0; mt < 2; mt++) {
        int r = wr + mt * 16 + (lane >> 2);
        float em0 = 0.f, em1 = 0.f;
#pragma unroll
        for (int nt = 0; nt < 6; nt++) {
            int pcol = col0 + wc + nt * 8 + (lane & 3) * 2;
            if (pcol < 160) {
                float bb0 = g_ob2perm[pcol];
                float bb1 = g_ob2perm[pcol + 1];
                float x = xt[pcol >> 1];
                float m0 = acc[mt][nt][0] + bb0;
                float s0 = acc[mt][nt][1] + bb1;
                float sp0 = (s0 > 15.f) ? s0 : __logf(1.f + __expf(s0));
                float sd0 = sp0 + 0.001f;
                float z0 = (x - m0) / sd0;
                em0 += -0.5f * z0 * z0 - __logf(sd0);
                float m1 = acc[mt][nt][2] + bb0;
                float s1 = acc[mt][nt][3] + bb1;
                float sp1 = (s1 > 15.f) ? s1 : __logf(1.f + __expf(s1));
                float sd1 = sp1 + 0.001f;
                float z1 = (x - m1) / sd1;
                em1 += -0.5f * z1 * z1 - __logf(sd1);
            } else if (pcol == 160) {
                tvbuf[r] = acc[mt][nt][0] + g_ob2perm[160];
                tvbuf[r + 8] = acc[mt][nt][2] + g_ob2perm[160];
            }
        }
        em0 += __shfl_xor_sync(0xffffffffu, em0, 1);
        em0 += __shfl_xor_sync(0xffffffffu, em0, 2);
        em1 += __shfl_xor_sync(0xffffffffu, em1, 1);
        em1 += __shfl_xor_sync(0xffffffffu, em1, 2);
        if ((lane & 3) == 0) {
            redbuf[r * 2 + cg] = em0;
            redbuf[(r + 8) * 2 + cg] = em1;
        }
    }
    __syncthreads();
    if (tid < 128) {
        float em = redbuf[tid * 2] + redbuf[tid * 2 + 1];
        if (nh == 0) {
            g_EMa[(size_t)tb * 128 + tid] = em;
        } else {
            g_EMb[(size_t)tb * 128 + tid] = em;
            float tv = tvbuf[tid];
            float s_move = 1.f / (1.f + __expf(-tv));
            float s_stay = 1.f - s_move;
            g_LS[(size_t)tb * 128 + tid] = __logf(fmaxf(s_stay, EPSC));
            g_LM[(size_t)tb * 128 + tid] = __logf(fmaxf(s_move, EPSC));
        }
    }
    __syncthreads();
    __threadfence();
    if (tid == 0) atomicAdd(&g_emdone[t], 1);
}

// alpha as a resident role
__device__ void alpha_role(float* __restrict__ out, const int* __restrict__ inputs_len,
                           const int* __restrict__ mel_lens) {
    int tid = threadIdx.x;
    int b = tid >> 5, l = tid & 31;
    int ilen = inputs_len[b], mlen = mel_lens[b];
    float la[4];
    float lp = 0.f;
    bool mk[4];
#pragma unroll
    for (int j = 0; j < 4; j++) mk[j] = (l * 4 + j) < ilen;
    for (int t = 0; t < Tt; t++) {
        if (tid == 0) {
            while (*((volatile int*)&g_emdone[t]) < 16) __nanosleep(128);
        }
        __syncthreads();
        int base = ((t << 3) + b) * 128 + l * 4;
        float4 ea = __ldcg((const float4*)&g_EMa[base]);
        float4 eb = __ldcg((const float4*)&g_EMb[base]);
        float4 ls4 = __ldcg((const float4*)&g_LS[base]);
        float4 lm4 = __ldcg((const float4*)&g_LM[base]);
        float em[4];
        {
            float era[4] = {ea.x + eb.x, ea.y + eb.y, ea.z + eb.z, ea.w + eb.w};
#pragma unroll
            for (int j = 0; j < 4; j++)
                em[j] = mk[j] ? (era[j] - 40.f * LOG2PI) : 0.f;
        }
        float v[4];
        if (t == 0) {
#pragma unroll
            for (int j = 0; j < 4; j++)
                v[j] = ((l == 0 && j == 0) ? 0.f : NEGV) + em[j];
        } else {
            float lau = __shfl_up_sync(0xffffffffu, la[3], 1);
            float lmu = __shfl_up_sync(0xffffffffu, lm4.w, 1);
            float lam1[4] = {lau, la[0], la[1], la[2]};
            float lmm1[4] = {lmu, lm4.x, lm4.y, lm4.z};
            float ls[4] = {ls4.x, ls4.y, ls4.z, ls4.w};
#pragma unroll
            for (int j = 0; j < 4; j++) {
                float stay = la[j] + ls[j];
                float leave = (l == 0 && j == 0) ? NEGV : lam1[j] + lmm1[j];
                float mx = fmaxf(stay, leave), mn = fminf(stay, leave);
                float ladd = mx + __logf(1.f + __expf(mn - mx));
                v[j] = em[j] + (mk[j] ? ladd : NEGV);
            }
        }
        float m = fmaxf(fmaxf(v[0], v[1]), fmaxf(v[2], v[3]));
#pragma unroll
        for (int off = 16; off; off >>= 1)
            m = fmaxf(m, __shfl_xor_sync(0xffffffffu, m, off));
        float s = __expf(v[0] - m) + __expf(v[1] - m) +
                  __expf(v[2] - m) + __expf(v[3] - m);
#pragma unroll
        for (int off = 16; off; off >>= 1)
            s += __shfl_xor_sync(0xffffffffu, s, off);
        float logc = m + __logf(s);
#pragma unroll
        for (int j = 0; j < 4; j++) la[j] = v[j] - logc;
        *(float4*)&out[8 + ((b << 8) + t) * 128 + l * 4] =
            make_float4(la[0], la[1], la[2], la[3]);
        if (l == 0 && t < mlen) lp += logc;
    }
    if (l == 0) out[b] = lp;
}

__global__ __launch_bounds__(256, 2) void k_fused(const float* __restrict__ whh,
                                                  const float* __restrict__ mels,
                                                  const float* __restrict__ ob0,
                                                  const float* __restrict__ ob1,
                                                  float* __restrict__ out,
                                                  const int* __restrict__ inputs_len,
                                                  const int* __restrict__ mel_lens) {
    extern __shared__ __align__(16) char smc[];
    __shared__ int s_job;
    int tid = threadIdx.x;
    if (blockIdx.x < 64) {
        lstm_role(smc, whh);
    } else if (blockIdx.x == 64) {
        alpha_role(out, inputs_len, mel_lens);
    }
    for (;;) {
        __syncthreads();
        if (tid == 0) s_job = atomicAdd(&g_jobctr, 1);
        __syncthreads();
        int j = s_job;
        if (j >= NJOBS) break;
        int jt = j / 33;
        int r = j - jt * 33;
        if (r == 0) {
            if (tid == 0)
                while (*((volatile int*)&g_release) < jt + 2) __nanosleep(64);
            __syncthreads();
            __threadfence();
            do_hp(smc, jt, ob0);
        } else if (r < 17) {
            int rr = r - 1;
            int tb = jt * 8 + (rr >> 1);
            if (tid == 0)
                while (*((volatile int*)&g_hpdone[jt]) == 0) __nanosleep(64);
            __syncthreads();
            __threadfence();
            do_g2(smc, tb, rr & 1, ob1);
        } else {
            int rr = r - 17;
            int tb = jt * 8 + (rr >> 1);
            if (tid == 0)
                while (*((volatile int*)&g_tbdone[tb]) < 2) __nanosleep(64);
            __syncthreads();
            __threadfence();
            do_g3(smc, tb, rr & 1, mels);
        }
    }
}

// ---------------- launch ----------------
extern "C" void kernel_launch(void* const* d_in, const int* in_sizes, int n_in,
                              void* d_out, int out_size) {
    const float* inputs = (const float*)d_in[0];
    const float* mels = (const float*)d_in[1];
    const float* w0 = (const float*)d_in[2];
    const float* w1p = (const float*)d_in[3];
    const float* wih = (const float*)d_in[4];
    const float* whh = (const float*)d_in[5];
    const float* bih = (const float*)d_in[6];
    const float* bhh = (const float*)d_in[7];
    const float* ow0 = (const float*)d_in[8];
    const float* ob0 = (const float*)d_in[9];
    const float* ow1 = (const float*)d_in[10];
    const float* ob1 = (const float*)d_in[11];
    const float* ow2 = (const float*)d_in[12];
    const float* ob2 = (const float*)d_in[13];
    const int* inputs_len = (const int*)d_in[14];
    const int* mel_lens = (const int*)d_in[15];
    float* out = (float*)d_out;

    cudaFuncSetAttribute(k_fused, cudaFuncAttributeMaxDynamicSharedMemorySize,
                         FU_SMEMB);
    cudaFuncSetAttribute(k_hgemm<0>, cudaFuncAttributeMaxDynamicSharedMemorySize,
                         HG_SMEMB);
    cudaFuncSetAttribute(k_hgemm<1>, cudaFuncAttributeMaxDynamicSharedMemorySize,
                         HG_SMEMB);

    float* pre0;  cudaGetSymbolAddress((void**)&pre0, g_PRE0);
    float* pre;   cudaGetSymbolAddress((void**)&pre, g_PRE);
    float* gi;    cudaGetSymbolAddress((void**)&gi, g_GI);
    float* zi;    cudaGetSymbolAddress((void**)&zi, g_ZI);
    float* arx;   cudaGetSymbolAddress((void**)&arx, g_ARX);
    float* w0t;   cudaGetSymbolAddress((void**)&w0t, g_W0T);
    float* bsum;  cudaGetSymbolAddress((void**)&bsum, g_bsum);
    u32* w1h;  cudaGetSymbolAddress((void**)&w1h, g_W1sp_h);
    u32* w1l;  cudaGetSymbolAddress((void**)&w1l, g_W1sp_l);
    u32* wihh; cudaGetSymbolAddress((void**)&wihh, g_WIHsp_h);
    u32* wihl; cudaGetSymbolAddress((void**)&wihl, g_WIHsp_l);
    u32* oeh;  cudaGetSymbolAddress((void**)&oeh, g_OW0Esp_h);
    u32* oel;  cudaGetSymbolAddress((void**)&oel, g_OW0Esp_l);

    k_prep<<<256, 256>>>(w0, w1p, wih, ow0, ow1, ow2, ob2, bih, bhh, mels);
    k_gemm<1><<<dim3(2, 32), 256>>>(pre0, arx, w0t, nullptr, 2048, 256, 96);
    k_hgemm<1><<<dim3(2, 16), 256, HG_SMEMB>>>(pre, pre0, w1h, w1l, nullptr, 256, 256);
    k_hgemm<0><<<dim3(16, 16), 256, HG_SMEMB>>>(gi, pre, wihh, wihl, bsum, 2048, 256);
    k_hgemm<0><<<dim3(2, 8), 256, HG_SMEMB>>>(zi, inputs, oeh, oel, nullptr, 256, 512);
    k_fused<<<296, 256, FU_SMEMB>>>(whh, mels, ob0, ob1, out, inputs_len, mel_lens);
    (void)in_sizes; (void)n_in; (void)out_size;
}

// round 17
// speedup vs baseline: 2.4608x; 1.0008x over previous
#include <cuda_runtime.h>
#include <cstdint>
#include <math.h>

#define Tt 256
#define NEGV -1e10f
#define EPSC 1e-4f
#define LOG2PI 1.8378770664093453f
#define NJOBS 8448
#define FU_SMEMB 111104
#define G2BUF 55296
#define G3BUF 50688

typedef unsigned long long ull;
typedef unsigned int u32;

#define PACK2(out, x) asm("mov.b64 %0, {%1, %1};" : "=l"(out) : "r"(__float_as_uint(x)))
#define UNPK(lo, hi, in) { unsigned int ulo, uhi; \
    asm("mov.b64 {%0, %1}, %2;" : "=r"(ulo), "=r"(uhi) : "l"(in)); \
    lo = __uint_as_float(ulo); hi = __uint_as_float(uhi); }
#define FMA2(d, a, b) asm("fma.rn.f32x2 %0, %1, %2, %0;" : "+l"(d) : "l"(a), "l"(b))
#define ADD2(d, a, b) asm("add.rn.f32x2 %0, %1, %2;" : "=l"(d) : "l"(a), "l"(b))

__device__ __forceinline__ u32 bf16_bits(float a) {
    u32 u = __float_as_uint(a);
    return (u + 0x7FFFu + ((u >> 16) & 1u)) >> 16;
}
// rounding split (prep only)
__device__ __forceinline__ void bfsplit2(float a0, float a1, u32& hi, u32& lo) {
    u32 h0 = bf16_bits(a0);
    u32 h1 = bf16_bits(a1);
    float h0f = __uint_as_float(h0 << 16);
    float h1f = __uint_as_float(h1 << 16);
    u32 l0 = bf16_bits(a0 - h0f);
    u32 l1 = bf16_bits(a1 - h1f);
    hi = (h1 << 16) | h0;
    lo = (l1 << 16) | l0;
}
// truncation split (hot path)
__device__ __forceinline__ void bfsplit2t(float a0, float a1, u32& hi, u32& lo) {
    u32 u0 = __float_as_uint(a0);
    u32 u1 = __float_as_uint(a1);
    float r0 = a0 - __uint_as_float(u0 & 0xFFFF0000u);
    float r1 = a1 - __uint_as_float(u1 & 0xFFFF0000u);
    hi = (u1 & 0xFFFF0000u) | (u0 >> 16);
    lo = (__float_as_uint(r1) & 0xFFFF0000u) | (__float_as_uint(r0) >> 16);
}
__device__ __forceinline__ u32 smem_to_u32(const void* p) {
    u32 a;
    asm("{ .reg .u64 t; cvta.to.shared.u64 t, %1; cvt.u32.u64 %0, t; }"
        : "=r"(a) : "l"(p));
    return a;
}
__device__ __forceinline__ void ldmx4(u32& r0, u32& r1, u32& r2, u32& r3, u32 addr) {
    asm volatile("ldmatrix.sync.aligned.m8n8.x4.shared.b16 {%0,%1,%2,%3}, [%4];"
                 : "=r"(r0), "=r"(r1), "=r"(r2), "=r"(r3) : "r"(addr));
}
__device__ __forceinline__ void mma_bf16(float* c, const u32* a, const u32* b) {
    asm volatile("mma.sync.aligned.m16n8k16.row.col.f32.bf16.bf16.f32 "
                 "{%0,%1,%2,%3}, {%4,%5,%6,%7}, {%8,%9}, {%0,%1,%2,%3};"
                 : "+f"(c[0]), "+f"(c[1]), "+f"(c[2]), "+f"(c[3])
                 : "r"(a[0]), "r"(a[1]), "r"(a[2]), "r"(a[3]),
                   "r"(b[0]), "r"(b[1]));
}

// ---------------- device scratch ----------------
__device__ float g_W0T[96 * 256];
__device__ float g_bsum[2048];
__device__ float g_ARX[2048 * 96];
__device__ float g_PRE0[2048 * 256];
__device__ float g_PRE[2048 * 256];
__device__ float g_GI[2048 * 2048];
__device__ float g_ZI[1024 * 256];
__device__ float g_H[2048 * 512];
__device__ float g_HP[2048 * 256];
__device__ float g_OW0MT[512 * 256];
__device__ float g_hping[2 * 4096];
__device__ float g_EMa[2048 * 128];
__device__ float g_EMb[2048 * 128];
__device__ float g_LS[2048 * 128];
__device__ float g_LM[2048 * 128];
__device__ float g_ob2perm[192];
__device__ u32 g_W1sp_h[256 * 128];
__device__ u32 g_W1sp_l[256 * 128];
__device__ u32 g_WIHsp_h[2048 * 128];
__device__ u32 g_WIHsp_l[2048 * 128];
__device__ u32 g_OW0Esp_h[256 * 256];
__device__ u32 g_OW0Esp_l[256 * 256];
__device__ unsigned short g_B1h[256 * 256];
__device__ unsigned short g_B2h[192 * 256];
__device__ u32 g_A2h[(size_t)2048 * 128 * 128];
__device__ u32 g_A2l[(size_t)2048 * 128 * 128];
__device__ int g_grp[8 * 32];
__device__ int g_master[32];
__device__ int g_release;
__device__ int g_jobctr;
__device__ int g_hpdone[256];
__device__ int g_tbdone[2048];
__device__ int g_emdone[256];

__device__ __forceinline__ float sigf(float x) { return 1.f / (1.f + __expf(-x)); }

// ---------------- prep ----------------
__global__ void k_prep(const float* __restrict__ w0, const float* __restrict__ w1p,
                       const float* __restrict__ wih, const float* __restrict__ ow0,
                       const float* __restrict__ ow1, const float* __restrict__ ow2,
                       const float* __restrict__ ob2, const float* __restrict__ bih,
                       const float* __restrict__ bhh, const float* __restrict__ mels) {
    int stride = gridDim.x * blockDim.x;
    int t0 = blockIdx.x * blockDim.x + threadIdx.x;
    for (int i = t0; i < 96 * 256; i += stride) {
        int k = i >> 8, p = i & 255;
        g_W0T[i] = (k < 80) ? w0[p * 80 + k] : 0.f;
    }
    for (int i = t0; i < 2048; i += stride) g_bsum[i] = bih[i] + bhh[i];
    for (int i = t0; i < 2048 * 96; i += stride) {
        int row = i / 96, d = i % 96;
        int t = row >> 3, b = row & 7;
        g_ARX[i] = (d < 80 && t > 0) ? mels[(b * 80 + d) * 256 + (t - 1)] : 0.f;
    }
    if (t0 < 8 * 32) g_grp[t0] = 0;
    if (t0 < 32) g_master[t0] = 0;
    if (t0 == 0) { g_release = 0; g_jobctr = 0; }
    if (t0 < 256) { g_hpdone[t0] = 0; g_emdone[t0] = 0; }
    for (int i = t0; i < 2048; i += stride) g_tbdone[i] = 0;
    for (int i = t0; i < 256 * 128; i += stride) {
        int n = i >> 7, kp = i & 127;
        u32 hi, lo;
        bfsplit2(w1p[n * 256 + 2 * kp], w1p[n * 256 + 2 * kp + 1], hi, lo);
        g_W1sp_h[i] = hi; g_W1sp_l[i] = lo;
    }
    for (int i = t0; i < 2048 * 128; i += stride) {
        int n = i >> 7, kp = i & 127;
        u32 hi, lo;
        bfsplit2(wih[n * 256 + 2 * kp], wih[n * 256 + 2 * kp + 1], hi, lo);
        g_WIHsp_h[i] = hi; g_WIHsp_l[i] = lo;
    }
    for (int i = t0; i < 256 * 256; i += stride) {
        int n = i >> 8, kp = i & 255;
        u32 hi, lo;
        bfsplit2(ow0[n * 1024 + 2 * kp], ow0[n * 1024 + 2 * kp + 1], hi, lo);
        g_OW0Esp_h[i] = hi; g_OW0Esp_l[i] = lo;
    }
    for (int i = t0; i < 512 * 256; i += stride) {
        int m = i >> 8, n = i & 255;
        g_OW0MT[i] = ow0[n * 1024 + 512 + m];
    }
    for (int i = t0; i < 65536; i += stride)
        g_B1h[i] = (unsigned short)bf16_bits(ow1[i]);
    for (int i = t0; i < 192 * 256; i += stride) {
        int n = i >> 8, k = i & 255;
        float w = 0.f;
        if (n < 160) {
            int sf = (n & 1) ? (80 + (n >> 1)) : (n >> 1);
            w = ow2[sf * 256 + k];
        } else if (n == 160) {
            w = ow2[160 * 256 + k];
        }
        g_B2h[i] = (unsigned short)bf16_bits(w);
    }
    for (int i = t0; i < 192; i += stride) {
        float v = 0.f;
        if (i < 160) v = ob2[(i & 1) ? (80 + (i >> 1)) : (i >> 1)];
        else if (i == 160) v = ob2[160];
        g_ob2perm[i] = v;
    }
}

// ---------------- f32x2 SGEMM (PRE0 only) ----------------
template <int ACT>
__global__ __launch_bounds__(256) void k_gemm(float* __restrict__ Cm,
                                              const float* __restrict__ Am,
                                              const float* __restrict__ BT,
                                              const float* __restrict__ bias,
                                              int R, int Ccols, int K) {
    __shared__ __align__(16) float As[32 * 68];
    __shared__ __align__(16) float Bs[32 * 128];
    int row0 = blockIdx.y * 64, col0 = blockIdx.x * 128;
    int tid = threadIdx.x;
    int tr = tid >> 4, tc = tid & 15;
    int r0 = tr * 4, c0 = tc * 8;
    ull acc0[8], acc1[8];
#pragma unroll
    for (int c = 0; c < 8; c++) { acc0[c] = 0ull; acc1[c] = 0ull; }
    for (int kt = 0; kt < K; kt += 32) {
        for (int i = tid; i < 2048; i += 256) {
            int r = i >> 5, k = i & 31;
            As[k * 68 + r] = Am[(row0 + r) * K + kt + k];
        }
        for (int i = tid; i < 4096; i += 256) {
            int k = i >> 7, c = i & 127;
            Bs[k * 128 + c] = BT[(kt + k) * Ccols + col0 + c];
        }
        __syncthreads();
#pragma unroll 8
        for (int k = 0; k < 32; k++) {
            ulonglong2 ap = *(const ulonglong2*)&As[k * 68 + r0];
            float4 b0 = *(const float4*)&Bs[k * 128 + c0];
            float4 b1 = *(const float4*)&Bs[k * 128 + c0 + 4];
            float wf[8] = {b0.x, b0.y, b0.z, b0.w, b1.x, b1.y, b1.z, b1.w};
#pragma unroll
            for (int c = 0; c < 8; c++) {
                ull wp;
                PACK2(wp, wf[c]);
                FMA2(acc0[c], ap.x, wp);
                FMA2(acc1[c], ap.y, wp);
            }
        }
        __syncthreads();
    }
#pragma unroll
    for (int c = 0; c < 8; c++) {
        int cc = col0 + c0 + c;
        float bb = bias ? bias[cc] : 0.f;
        float v0, v1, v2, v3;
        UNPK(v0, v1, acc0[c]);
        UNPK(v2, v3, acc1[c]);
        v0 += bb; v1 += bb; v2 += bb; v3 += bb;
        if (ACT) { v0 = fmaxf(v0, 0.f); v1 = fmaxf(v1, 0.f);
                   v2 = fmaxf(v2, 0.f); v3 = fmaxf(v3, 0.f); }
        Cm[(row0 + r0 + 0) * Ccols + cc] = v0;
        Cm[(row0 + r0 + 1) * Ccols + cc] = v1;
        Cm[(row0 + r0 + 2) * Ccols + cc] = v2;
        Cm[(row0 + r0 + 3) * Ccols + cc] = v3;
    }
}

// ---------------- generic HMMA GEMM (PRE, GI, ZI; 3-term) ----------------
#define HG_SMEMB 73728

template <int RELU>
__global__ __launch_bounds__(256, 1) void k_hgemm(float* __restrict__ Cm,
                                                  const float* __restrict__ Am,
                                                  const u32* __restrict__ Bh,
                                                  const u32* __restrict__ Bl,
                                                  const float* __restrict__ bias,
                                                  int Ccols, int K) {
    extern __shared__ __align__(16) char smh[];
    u32 sbase = smem_to_u32(smh);
    u32* Ah32 = (u32*)smh;
    u32* Al32 = (u32*)(smh + 18432);
    u32* Bh32 = (u32*)(smh + 36864);
    u32* Bl32 = (u32*)(smh + 55296);
    int row0 = blockIdx.y * 128, col0 = blockIdx.x * 128;
    int tid = threadIdx.x;
    int warp = tid >> 5, lane = tid & 31;
    int wr = (warp & 3) * 32;
    int wc = (warp >> 2) * 64;
    int Kh = K >> 1;
    float acc[2][8][4];
#pragma unroll
    for (int mt = 0; mt < 2; mt++)
#pragma unroll
        for (int nt = 0; nt < 8; nt++)
#pragma unroll
            for (int q = 0; q < 4; q++) acc[mt][nt][q] = 0.f;
    u32 lmrow = (u32)(lane & 15);
    u32 lmk = (u32)((lane >> 4) << 3);

    for (int kc = 0; kc < (K >> 6); kc++) {
        int k0 = kc * 64;
        for (int i = tid; i < 4096; i += 256) {
            int r = i >> 5, kp = i & 31;
            float2 av = *(const float2*)&Am[(size_t)(row0 + r) * K + k0 + 2 * kp];
            u32 hi, lo;
            bfsplit2t(av.x, av.y, hi, lo);
            Ah32[r * 36 + kp] = hi;
            Al32[r * 36 + kp] = lo;
        }
        for (int i = tid; i < 4096; i += 256) {
            int n = i >> 5, kp = i & 31;
            size_t gsrc = (size_t)(col0 + n) * Kh + (k0 >> 1) + kp;
            Bh32[n * 36 + kp] = Bh[gsrc];
            Bl32[n * 36 + kp] = Bl[gsrc];
        }
        __syncthreads();
#pragma unroll
        for (int ks = 0; ks < 4; ks++) {
            u32 kk = (u32)(ks * 16);
            u32 a_h[2][4], a_l[2][4];
#pragma unroll
            for (int mt = 0; mt < 2; mt++) {
                u32 ad = sbase + (((u32)(wr + mt * 16) + lmrow) * 72 + kk + lmk) * 2;
                ldmx4(a_h[mt][0], a_h[mt][1], a_h[mt][2], a_h[mt][3], ad);
                ldmx4(a_l[mt][0], a_l[mt][1], a_l[mt][2], a_l[mt][3], ad + 18432);
            }
            u32 b_h[8][2], b_l[8][2];
#pragma unroll
            for (int np = 0; np < 4; np++) {
                u32 bd = sbase + 36864 +
                         (((u32)(wc + np * 16) + lmrow) * 72 + kk + lmk) * 2;
                u32 r0, r1, r2, r3;
                ldmx4(r0, r1, r2, r3, bd);
                b_h[np * 2][0] = r0; b_h[np * 2][1] = r2;
                b_h[np * 2 + 1][0] = r1; b_h[np * 2 + 1][1] = r3;
                ldmx4(r0, r1, r2, r3, bd + 18432);
                b_l[np * 2][0] = r0; b_l[np * 2][1] = r2;
                b_l[np * 2 + 1][0] = r1; b_l[np * 2 + 1][1] = r3;
            }
#pragma unroll
            for (int mt = 0; mt < 2; mt++)
#pragma unroll
                for (int nt = 0; nt < 8; nt++) {
                    mma_bf16(acc[mt][nt], a_h[mt], b_h[nt]);
                    mma_bf16(acc[mt][nt], a_l[mt], b_h[nt]);
                    mma_bf16(acc[mt][nt], a_h[mt], b_l[nt]);
                }
        }
        __syncthreads();
    }
#pragma unroll
    for (int mt = 0; mt < 2; mt++) {
        int r = wr + mt * 16 + (lane >> 2);
#pragma unroll
        for (int nt = 0; nt < 8; nt++) {
            int gc = col0 + wc + nt * 8 + (lane & 3) * 2;
            float bb0 = bias ? bias[gc] : 0.f;
            float bb1 = bias ? bias[gc + 1] : 0.f;
            float v0 = acc[mt][nt][0] + bb0;
            float v1 = acc[mt][nt][1] + bb1;
            float v2 = acc[mt][nt][2] + bb0;
            float v3 = acc[mt][nt][3] + bb1;
            if (RELU) { v0 = fmaxf(v0, 0.f); v1 = fmaxf(v1, 0.f);
                        v2 = fmaxf(v2, 0.f); v3 = fmaxf(v3, 0.f); }
            Cm[(size_t)(row0 + r) * Ccols + gc] = v0;
            Cm[(size_t)(row0 + r) * Ccols + gc + 1] = v1;
            Cm[(size_t)(row0 + r + 8) * Ccols + gc] = v2;
            Cm[(size_t)(row0 + r + 8) * Ccols + gc + 1] = v3;
        }
    }
}

// ================= fused persistent kernel =================
__device__ __forceinline__ void lbar2(int target) {
    __syncthreads();
    if (threadIdx.x == 0) {
        __threadfence();
        int g = blockIdx.x & 7;
        int old = atomicAdd(&g_grp[g * 32], 1);
        if (old == target * 8 - 1) {
            int mo = atomicAdd(&g_master[0], 1);
            if (mo == target * 8 - 1) {
                atomicExch(&g_release, target);
            }
        }
        while (*((volatile int*)&g_release) < target) __nanosleep(16);
        __threadfence();
    }
    __syncthreads();
}

__device__ void lstm_role(char* smc, const float* __restrict__ whh) {
    float* sm = (float*)smc;
    float* Wsl = sm;
    float* hs = sm + 16512;
    ull* part = (ull*)(sm + 20608);
    int tid = threadIdx.x;
    int m0 = blockIdx.x * 8;
    for (int i = tid; i < 32 * 512; i += 256) {
        int row = i >> 9, k = i & 511;
        int gate = row >> 3, ml = row & 7;
        Wsl[row * 516 + k] = whh[(gate * 512 + m0 + ml) * 512 + k];
    }
    if (tid < 64) __stcg(&g_hping[blockIdx.x * 64 + tid], 0.f);
    int w = tid >> 5, l = tid & 31;
    int g = w & 3;
    int khf = w >> 2;
    int k0 = khf * 256 + l;
    int ml_u = tid >> 3, b_u = tid & 7;
    float c_reg = 0.f;
    lbar2(1);
    for (int t = 0; t < Tt; t++) {
        int cur = t & 1, nxt = cur ^ 1;
        float gi0 = 0.f, gi1 = 0.f, gi2 = 0.f, gi3 = 0.f;
        if (tid < 64) {
            const float* gip = &g_GI[(t * 8 + b_u) * 2048 + m0 + ml_u];
            gi0 = __ldg(gip);
            gi1 = __ldg(gip + 512);
            gi2 = __ldg(gip + 1024);
            gi3 = __ldg(gip + 1536);
        }
        for (int i = tid; i < 2048; i += 256)
            ((float2*)hs)[i] = __ldcg(&((const float2*)g_hping)[cur * 2048 + i]);
        __syncthreads();
        ull acc[32];
#pragma unroll
        for (int i = 0; i < 32; i++) acc[i] = 0ull;
#pragma unroll
        for (int j = 0; j < 8; j++) {
            int k = k0 + 32 * j;
            ulonglong2 h01 = *(const ulonglong2*)&hs[k * 8];
            ulonglong2 h23 = *(const ulonglong2*)&hs[k * 8 + 4];
            ull hv0 = h01.x, hv1 = h01.y, hv2 = h23.x, hv3 = h23.y;
#pragma unroll
            for (int r = 0; r < 8; r++) {
                float wv = Wsl[(g * 8 + r) * 516 + k];
                ull wp;
                PACK2(wp, wv);
                FMA2(acc[r * 4 + 0], wp, hv0);
                FMA2(acc[r * 4 + 1], wp, hv1);
                FMA2(acc[r * 4 + 2], wp, hv2);
                FMA2(acc[r * 4 + 3], wp, hv3);
            }
        }
#define REDST(OFF, CNT)                                                    \
        {                                                                  \
            bool hib = (l & OFF) != 0;                                     \
            _Pragma("unroll")                                              \
            for (int i = 0; i < CNT; i++) {                                \
                ull snd = hib ? acc[i] : acc[i + CNT];                     \
                ull rcv = __shfl_xor_sync(0xffffffffu, snd, OFF);          \
                ull kp = hib ? acc[i + CNT] : acc[i];                      \
                ADD2(acc[i], kp, rcv);                                     \
            }                                                              \
        }
        REDST(16, 16) REDST(8, 8) REDST(4, 4) REDST(2, 2) REDST(1, 1)
#undef REDST
        part[w * 32 + l] = acc[0];
        __syncthreads();
        if (tid < 64) {
            int p = b_u >> 1, hi = b_u & 1;
            int L = ml_u * 4 + p;
            float gv[4];
#pragma unroll
            for (int gate = 0; gate < 4; gate++) {
                ull s;
                ADD2(s, part[gate * 32 + L], part[(gate + 4) * 32 + L]);
                float lo, hif;
                UNPK(lo, hif, s);
                gv[gate] = hi ? hif : lo;
            }
            float ig = gv[0] + gi0;
            float fg = gv[1] + gi1;
            float gg = gv[2] + gi2;
            float og = gv[3] + gi3;
            float cn = sigf(fg) * c_reg + sigf(ig) * tanhf(gg);
            float h = sigf(og) * tanhf(cn);
            c_reg = cn;
            __stcg(&g_hping[nxt * 4096 + (m0 + ml_u) * 8 + b_u], h);
            __stcg(&g_H[(t * 8 + b_u) * 512 + m0 + ml_u], h);
        }
        lbar2(t + 2);
    }
}

// batched HP: one job computes HP for all 8 b of time-step t
__device__ void do_hp(char* smc, int t, const float* __restrict__ ob0) {
    float* Hs = (float*)smc;
    int tid = threadIdx.x;
    for (int i = tid; i < 4096; i += 256)
        Hs[i] = __ldcg(&g_H[(size_t)t * 4096 + i]);
    __syncthreads();
    float a[8];
#pragma unroll
    for (int b = 0; b < 8; b++) a[b] = 0.f;
    const float* W = g_OW0MT;
    for (int m = 0; m < 512; m += 4) {
        float w0 = __ldg(&W[m * 256 + tid]);
        float w1 = __ldg(&W[(m + 1) * 256 + tid]);
        float w2 = __ldg(&W[(m + 2) * 256 + tid]);
        float w3 = __ldg(&W[(m + 3) * 256 + tid]);
#pragma unroll
        for (int b = 0; b < 8; b++) {
            float4 h4 = *(const float4*)&Hs[b * 512 + m];
            a[b] = fmaf(h4.x, w0, fmaf(h4.y, w1, fmaf(h4.z, w2, fmaf(h4.w, w3, a[b]))));
        }
    }
    float bb = ob0[tid];
#pragma unroll
    for (int b = 0; b < 8; b++)
        g_HP[(size_t)(t * 8 + b) * 256 + tid] = a[b] + bb;
    __syncthreads();
    __threadfence();
    if (tid == 0) atomicExch(&g_hpdone[t], 1);
}

// ---- g2 staging helper (into buffer p) ----
__device__ __forceinline__ void g2_stage(char* smc2, int p, int tb, int b, int col0,
                                         int kc) {
    u32* Ah32 = (u32*)(smc2 + p * G2BUF);
    u32* Al32 = (u32*)(smc2 + p * G2BUF + 18432);
    u32* Bh32 = (u32*)(smc2 + p * G2BUF + 36864);
    const u32* gB1h = (const u32*)g_B1h;
    int k0 = kc * 64;
    int tid = threadIdx.x;
    for (int i = tid; i < 4096; i += 256) {
        int r = i >> 5, kp = i & 31;
        float2 za = *(const float2*)&g_ZI[(size_t)(b * 128 + r) * 256 + k0 + 2 * kp];
        float2 hp = __ldcg((const float2*)&g_HP[(size_t)tb * 256 + k0 + 2 * kp]);
        float a0 = fmaxf(za.x + hp.x, 0.f);
        float a1 = fmaxf(za.y + hp.y, 0.f);
        u32 hi, lo;
        bfsplit2t(a0, a1, hi, lo);
        Ah32[r * 36 + kp] = hi;
        Al32[r * 36 + kp] = lo;
    }
    for (int i = tid; i < 4096; i += 256) {
        int n = i >> 5, kp = i & 31;
        size_t gsrc = (size_t)(col0 + n) * 128 + (k0 >> 1) + kp;
        Bh32[n * 36 + kp] = gB1h[gsrc];
    }
}

// g2: 2-term, double-buffered staging
__device__ void do_g2(char* smc2, int tb, int half, const float* __restrict__ ob1) {
    u32 sbase = smem_to_u32(smc2);
    int col0 = half * 128;
    int b = tb & 7;
    int tid = threadIdx.x;
    int warp = tid >> 5, lane = tid & 31;
    int wr = (warp & 3) * 32;
    int wc = (warp >> 2) * 64;
    float acc[2][8][4];
#pragma unroll
    for (int mt = 0; mt < 2; mt++)
#pragma unroll
        for (int nt = 0; nt < 8; nt++)
#pragma unroll
            for (int q = 0; q < 4; q++) acc[mt][nt][q] = 0.f;
    u32 lmrow = (u32)(lane & 15);
    u32 lmk = (u32)((lane >> 4) << 3);

    g2_stage(smc2, 0, tb, b, col0, 0);
    __syncthreads();
    for (int kc = 0; kc < 4; kc++) {
        int cur = kc & 1;
        if (kc < 3) g2_stage(smc2, cur ^ 1, tb, b, col0, kc + 1);
        u32 bb0 = sbase + (u32)(cur * G2BUF);
#pragma unroll
        for (int ks = 0; ks < 4; ks++) {
            u32 kk = (u32)(ks * 16);
            u32 a_h[2][4], a_l[2][4];
#pragma unroll
            for (int mt = 0; mt < 2; mt++) {
                u32 ad = bb0 + (((u32)(wr + mt * 16) + lmrow) * 72 + kk + lmk) * 2;
                ldmx4(a_h[mt][0], a_h[mt][1], a_h[mt][2], a_h[mt][3], ad);
                ldmx4(a_l[mt][0], a_l[mt][1], a_l[mt][2], a_l[mt][3], ad + 18432);
            }
            u32 b_h[8][2];
#pragma unroll
            for (int np = 0; np < 4; np++) {
                u32 bd = bb0 + 36864 +
                         (((u32)(wc + np * 16) + lmrow) * 72 + kk + lmk) * 2;
                u32 r0, r1, r2, r3;
                ldmx4(r0, r1, r2, r3, bd);
                b_h[np * 2][0] = r0; b_h[np * 2][1] = r2;
                b_h[np * 2 + 1][0] = r1; b_h[np * 2 + 1][1] = r3;
            }
#pragma unroll
            for (int mt = 0; mt < 2; mt++)
#pragma unroll
                for (int nt = 0; nt < 8; nt++) {
                    mma_bf16(acc[mt][nt], a_h[mt], b_h[nt]);
                    mma_bf16(acc[mt][nt], a_l[mt], b_h[nt]);
                }
        }
        __syncthreads();
    }
#pragma unroll
    for (int mt = 0; mt < 2; mt++) {
        int r = wr + mt * 16 + (lane >> 2);
#pragma unroll
        for (int nt = 0; nt < 8; nt++) {
            int col = wc + nt * 8 + (lane & 3) * 2;
            int gc = col0 + col;
            float bb0 = ob1[gc], bb1 = ob1[gc + 1];
            float v0 = fmaxf(acc[mt][nt][0] + bb0, 0.f);
            float v1 = fmaxf(acc[mt][nt][1] + bb1, 0.f);
            u32 hp, lp;
            bfsplit2t(v0, v1, hp, lp);
            size_t dst = ((size_t)tb * 128 + r) * 128 + (gc >> 1);
            g_A2h[dst] = hp;
            g_A2l[dst] = lp;
            v0 = fmaxf(acc[mt][nt][2] + bb0, 0.f);
            v1 = fmaxf(acc[mt][nt][3] + bb1, 0.f);
            bfsplit2t(v0, v1, hp, lp);
            dst = ((size_t)tb * 128 + r + 8) * 128 + (gc >> 1);
            g_A2h[dst] = hp;
            g_A2l[dst] = lp;
        }
    }
    __syncthreads();
    __threadfence();
    if (tid == 0) atomicAdd(&g_tbdone[tb], 1);
}

// ---- g3 staging helper ----
__device__ __forceinline__ void g3_stage(char* smc3, int p, int tb, int col0, int kc) {
    u32* Ah32 = (u32*)(smc3 + p * G3BUF);
    u32* Al32 = (u32*)(smc3 + p * G3BUF + 18432);
    u32* Bh32 = (u32*)(smc3 + p * G3BUF + 36864);
    const u32* gB2h = (const u32*)g_B2h;
    int k0 = kc * 64;
    int tid = threadIdx.x;
    for (int i = tid; i < 4096; i += 256) {
        int r = i >> 5, kp = i & 31;
        size_t gsrc = ((size_t)tb * 128 + r) * 128 + (k0 >> 1) + kp;
        Ah32[r * 36 + kp] = __ldcg(&g_A2h[gsrc]);
        Al32[r * 36 + kp] = __ldcg(&g_A2l[gsrc]);
    }
    for (int i = tid; i < 3072; i += 256) {
        int n = i >> 5, kp = i & 31;
        size_t gsrc = (size_t)(col0 + n) * 128 + (k0 >> 1) + kp;
        Bh32[n * 36 + kp] = gB2h[gsrc];
    }
}

// g3: 2-term + emission epilogue, double-buffered staging
__device__ void do_g3(char* smc3, int tb, int nh, const float* __restrict__ mels) {
    u32 sbase = smem_to_u32(smc3);
    float* xt = (float*)(smc3 + 2 * G3BUF);
    float* redbuf = (float*)(smc3 + 2 * G3BUF + 384);
    float* tvbuf = (float*)(smc3 + 2 * G3BUF + 1408);
    int col0 = nh * 96;
    int t = tb >> 3, b = tb & 7;
    int tid = threadIdx.x;
    int warp = tid >> 5, lane = tid & 31;
    int wr = (warp & 3) * 32;
    int wc = (warp >> 2) * 48;
    int cg = warp >> 2;
    if (tid < 80) xt[tid] = mels[(b * 80 + tid) * 256 + t];
    float acc[2][6][4];
#pragma unroll
    for (int mt = 0; mt < 2; mt++)
#pragma unroll
        for (int nt = 0; nt < 6; nt++)
#pragma unroll
            for (int q = 0; q < 4; q++) acc[mt][nt][q] = 0.f;
    u32 lmrow = (u32)(lane & 15);
    u32 lmk = (u32)((lane >> 4) << 3);

    g3_stage(smc3, 0, tb, col0, 0);
    __syncthreads();
    for (int kc = 0; kc < 4; kc++) {
        int cur = kc & 1;
        if (kc < 3) g3_stage(smc3, cur ^ 1, tb, col0, kc + 1);
        u32 bb0 = sbase + (u32)(cur * G3BUF);
#pragma unroll
        for (int ks = 0; ks < 4; ks++) {
            u32 kk = (u32)(ks * 16);
            u32 a_h[2][4], a_l[2][4];
#pragma unroll
            for (int mt = 0; mt < 2; mt++) {
                u32 ad = bb0 + (((u32)(wr + mt * 16) + lmrow) * 72 + kk + lmk) * 2;
                ldmx4(a_h[mt][0], a_h[mt][1], a_h[mt][2], a_h[mt][3], ad);
                ldmx4(a_l[mt][0], a_l[mt][1], a_l[mt][2], a_l[mt][3], ad + 18432);
            }
            u32 b_h[6][2];
#pragma unroll
            for (int np = 0; np < 3; np++) {
                u32 bd = bb0 + 36864 +
                         (((u32)(wc + np * 16) + lmrow) * 72 + kk + lmk) * 2;
                u32 r0, r1, r2, r3;
                ldmx4(r0, r1, r2, r3, bd);
                b_h[np * 2][0] = r0; b_h[np * 2][1] = r2;
                b_h[np * 2 + 1][0] = r1; b_h[np * 2 + 1][1] = r3;
            }
#pragma unroll
            for (int mt = 0; mt < 2; mt++)
#pragma unroll
                for (int nt = 0; nt < 6; nt++) {
                    mma_bf16(acc[mt][nt], a_h[mt], b_h[nt]);
                    mma_bf16(acc[mt][nt], a_l[mt], b_h[nt]);
                }
        }
        __syncthreads();
    }
#pragma unroll
    for (int mt = 0; mt < 2; mt++) {
        int r = wr + mt * 16 + (lane >> 2);
        float em0 = 0.f, em1 = 0.f;
#pragma unroll
        for (int nt = 0; nt < 6; nt++) {
            int pcol = col0 + wc + nt * 8 + (lane & 3) * 2;
            if (pcol < 160) {
                float bb0 = g_ob2perm[pcol];
                float bb1 = g_ob2perm[pcol + 1];
                float x = xt[pcol >> 1];
                float m0 = acc[mt][nt][0] + bb0;
                float s0 = acc[mt][nt][1] + bb1;
                float sp0 = (s0 > 15.f) ? s0 : __logf(1.f + __expf(s0));
                float sd0 = sp0 + 0.001f;
                float z0 = (x - m0) / sd0;
                em0 += -0.5f * z0 * z0 - __logf(sd0);
                float m1 = acc[mt][nt][2] + bb0;
                float s1 = acc[mt][nt][3] + bb1;
                float sp1 = (s1 > 15.f) ? s1 : __logf(1.f + __expf(s1));
                float sd1 = sp1 + 0.001f;
                float z1 = (x - m1) / sd1;
                em1 += -0.5f * z1 * z1 - __logf(sd1);
            } else if (pcol == 160) {
                tvbuf[r] = acc[mt][nt][0] + g_ob2perm[160];
                tvbuf[r + 8] = acc[mt][nt][2] + g_ob2perm[160];
            }
        }
        em0 += __shfl_xor_sync(0xffffffffu, em0, 1);
        em0 += __shfl_xor_sync(0xffffffffu, em0, 2);
        em1 += __shfl_xor_sync(0xffffffffu, em1, 1);
        em1 += __shfl_xor_sync(0xffffffffu, em1, 2);
        if ((lane & 3) == 0) {
            redbuf[r * 2 + cg] = em0;
            redbuf[(r + 8) * 2 + cg] = em1;
        }
    }
    __syncthreads();
    if (tid < 128) {
        float em = redbuf[tid * 2] + redbuf[tid * 2 + 1];
        if (nh == 0) {
            g_EMa[(size_t)tb * 128 + tid] = em;
        } else {
            g_EMb[(size_t)tb * 128 + tid] = em;
            float tv = tvbuf[tid];
            float s_move = 1.f / (1.f + __expf(-tv));
            float s_stay = 1.f - s_move;
            g_LS[(size_t)tb * 128 + tid] = __logf(fmaxf(s_stay, EPSC));
            g_LM[(size_t)tb * 128 + tid] = __logf(fmaxf(s_move, EPSC));
        }
    }
    __syncthreads();
    __threadfence();
    if (tid == 0) atomicAdd(&g_emdone[t], 1);
}

// alpha as a resident role
__device__ void alpha_role(float* __restrict__ out, const int* __restrict__ inputs_len,
                           const int* __restrict__ mel_lens) {
    int tid = threadIdx.x;
    int b = tid >> 5, l = tid & 31;
    int ilen = inputs_len[b], mlen = mel_lens[b];
    float la[4];
    float lp = 0.f;
    bool mk[4];
#pragma unroll
    for (int j = 0; j < 4; j++) mk[j] = (l * 4 + j) < ilen;
    for (int t = 0; t < Tt; t++) {
        if (tid == 0) {
            while (*((volatile int*)&g_emdone[t]) < 16) __nanosleep(128);
        }
        __syncthreads();
        int base = ((t << 3) + b) * 128 + l * 4;
        float4 ea = __ldcg((const float4*)&g_EMa[base]);
        float4 eb = __ldcg((const float4*)&g_EMb[base]);
        float4 ls4 = __ldcg((const float4*)&g_LS[base]);
        float4 lm4 = __ldcg((const float4*)&g_LM[base]);
        float em[4];
        {
            float era[4] = {ea.x + eb.x, ea.y + eb.y, ea.z + eb.z, ea.w + eb.w};
#pragma unroll
            for (int j = 0; j < 4; j++)
                em[j] = mk[j] ? (era[j] - 40.f * LOG2PI) : 0.f;
        }
        float v[4];
        if (t == 0) {
#pragma unroll
            for (int j = 0; j < 4; j++)
                v[j] = ((l == 0 && j == 0) ? 0.f : NEGV) + em[j];
        } else {
            float lau = __shfl_up_sync(0xffffffffu, la[3], 1);
            float lmu = __shfl_up_sync(0xffffffffu, lm4.w, 1);
            float lam1[4] = {lau, la[0], la[1], la[2]};
            float lmm1[4] = {lmu, lm4.x, lm4.y, lm4.z};
            float ls[4] = {ls4.x, ls4.y, ls4.z, ls4.w};
#pragma unroll
            for (int j = 0; j < 4; j++) {
                float stay = la[j] + ls[j];
                float leave = (l == 0 && j == 0) ? NEGV : lam1[j] + lmm1[j];
                float mx = fmaxf(stay, leave), mn = fminf(stay, leave);
                float ladd = mx + __logf(1.f + __expf(mn - mx));
                v[j] = em[j] + (mk[j] ? ladd : NEGV);
            }
        }
        float m = fmaxf(fmaxf(v[0], v[1]), fmaxf(v[2], v[3]));
#pragma unroll
        for (int off = 16; off; off >>= 1)
            m = fmaxf(m, __shfl_xor_sync(0xffffffffu, m, off));
        float s = __expf(v[0] - m) + __expf(v[1] - m) +
                  __expf(v[2] - m) + __expf(v[3] - m);
#pragma unroll
        for (int off = 16; off; off >>= 1)
            s += __shfl_xor_sync(0xffffffffu, s, off);
        float logc = m + __logf(s);
#pragma unroll
        for (int j = 0; j < 4; j++) la[j] = v[j] - logc;
        *(float4*)&out[8 + ((b << 8) + t) * 128 + l * 4] =
            make_float4(la[0], la[1], la[2], la[3]);
        if (l == 0 && t < mlen) lp += logc;
    }
    if (l == 0) out[b] = lp;
}

__global__ __launch_bounds__(256, 2) void k_fused(const float* __restrict__ whh,
                                                  const float* __restrict__ mels,
                                                  const float* __restrict__ ob0,
                                                  const float* __restrict__ ob1,
                                                  float* __restrict__ out,
                                                  const int* __restrict__ inputs_len,
                                                  const int* __restrict__ mel_lens) {
    extern __shared__ __align__(16) char smc[];
    __shared__ int s_job;
    int tid = threadIdx.x;
    if (blockIdx.x < 64) {
        lstm_role(smc, whh);
    } else if (blockIdx.x == 64) {
        alpha_role(out, inputs_len, mel_lens);
    }
    for (;;) {
        __syncthreads();
        if (tid == 0) s_job = atomicAdd(&g_jobctr, 1);
        __syncthreads();
        int j = s_job;
        if (j >= NJOBS) break;
        int jt = j / 33;
        int r = j - jt * 33;
        if (r == 0) {
            if (tid == 0)
                while (*((volatile int*)&g_release) < jt + 2) __nanosleep(64);
            __syncthreads();
            __threadfence();
            do_hp(smc, jt, ob0);
        } else if (r < 17) {
            int rr = r - 1;
            int tb = jt * 8 + (rr >> 1);
            if (tid == 0)
                while (*((volatile int*)&g_hpdone[jt]) == 0) __nanosleep(64);
            __syncthreads();
            __threadfence();
            do_g2(smc, tb, rr & 1, ob1);
        } else {
            int rr = r - 17;
            int tb = jt * 8 + (rr >> 1);
            if (tid == 0)
                while (*((volatile int*)&g_tbdone[tb]) < 2) __nanosleep(64);
            __syncthreads();
            __threadfence();
            do_g3(smc, tb, rr & 1, mels);
        }
    }
}

// ---------------- launch ----------------
extern "C" void kernel_launch(void* const* d_in, const int* in_sizes, int n_in,
                              void* d_out, int out_size) {
    const float* inputs = (const float*)d_in[0];
    const float* mels = (const float*)d_in[1];
    const float* w0 = (const float*)d_in[2];
    const float* w1p = (const float*)d_in[3];
    const float* wih = (const float*)d_in[4];
    const float* whh = (const float*)d_in[5];
    const float* bih = (const float*)d_in[6];
    const float* bhh = (const float*)d_in[7];
    const float* ow0 = (const float*)d_in[8];
    const float* ob0 = (const float*)d_in[9];
    const float* ow1 = (const float*)d_in[10];
    const float* ob1 = (const float*)d_in[11];
    const float* ow2 = (const float*)d_in[12];
    const float* ob2 = (const float*)d_in[13];
    const int* inputs_len = (const int*)d_in[14];
    const int* mel_lens = (const int*)d_in[15];
    float* out = (float*)d_out;

    cudaFuncSetAttribute(k_fused, cudaFuncAttributeMaxDynamicSharedMemorySize,
                         FU_SMEMB);
    cudaFuncSetAttribute(k_hgemm<0>, cudaFuncAttributeMaxDynamicSharedMemorySize,
                         HG_SMEMB);
    cudaFuncSetAttribute(k_hgemm<1>, cudaFuncAttributeMaxDynamicSharedMemorySize,
                         HG_SMEMB);

    float* pre0;  cudaGetSymbolAddress((void**)&pre0, g_PRE0);
    float* pre;   cudaGetSymbolAddress((void**)&pre, g_PRE);
    float* gi;    cudaGetSymbolAddress((void**)&gi, g_GI);
    float* zi;    cudaGetSymbolAddress((void**)&zi, g_ZI);
    float* arx;   cudaGetSymbolAddress((void**)&arx, g_ARX);
    float* w0t;   cudaGetSymbolAddress((void**)&w0t, g_W0T);
    float* bsum;  cudaGetSymbolAddress((void**)&bsum, g_bsum);
    u32* w1h;  cudaGetSymbolAddress((void**)&w1h, g_W1sp_h);
    u32* w1l;  cudaGetSymbolAddress((void**)&w1l, g_W1sp_l);
    u32* wihh; cudaGetSymbolAddress((void**)&wihh, g_WIHsp_h);
    u32* wihl; cudaGetSymbolAddress((void**)&wihl, g_WIHsp_l);
    u32* oeh;  cudaGetSymbolAddress((void**)&oeh, g_OW0Esp_h);
    u32* oel;  cudaGetSymbolAddress((void**)&oel, g_OW0Esp_l);

    k_prep<<<256, 256>>>(w0, w1p, wih, ow0, ow1, ow2, ob2, bih, bhh, mels);
    k_gemm<1><<<dim3(2, 32), 256>>>(pre0, arx, w0t, nullptr, 2048, 256, 96);
    k_hgemm<1><<<dim3(2, 16), 256, HG_SMEMB>>>(pre, pre0, w1h, w1l, nullptr, 256, 256);
    k_hgemm<0><<<dim3(16, 16), 256, HG_SMEMB>>>(gi, pre, wihh, wihl, bsum, 2048, 256);
    k_hgemm<0><<<dim3(2, 8), 256, HG_SMEMB>>>(zi, inputs, oeh, oel, nullptr, 256, 512);
    k_fused<<<296, 256, FU_SMEMB>>>(whh, mels, ob0, ob1, out, inputs_len, mel_lens);
    (void)in_sizes; (void)n_in; (void)out_size;
}